// round 11
// baseline (speedup 1.0000x reference)
#include <cuda_runtime.h>
#include <cuda_bf16.h>
#include <cstdint>

namespace {
constexpr int B = 4, S = 2048, D = 64, KS = 8;
constexpr float SCALE = 0.022097086912079612f;  // 1/sqrt(2048)
constexpr float NEGBIG = -3.402823466e38f;
}

// ---------------- scratch ----------------
__device__ __nv_bfloat16 g_wqh[(size_t)S * S], g_wql[(size_t)S * S];
__device__ __nv_bfloat16 g_wvh[(size_t)S * S], g_wvl[(size_t)S * S];
__device__ __nv_bfloat16 g_xth[(size_t)B * D * S], g_xtl[(size_t)B * D * S];
__device__ float g_k2part[(size_t)4 * 2 * B * S * D];  // [kq][mat][b][s][d]
__device__ float g_Q[(size_t)B * S * D];
__device__ float g_V[(size_t)B * S * D];
__device__ float g_scores[(size_t)B * S * S];
__device__ float g_partM[B * 16 * S];
__device__ float g_partZ[B * 16 * S];
__device__ float g_colC[B * S];
__device__ float g_part[(size_t)KS * B * S * D];

// ---- m16n8k16 bf16 HMMA (baseline PTX, works on sm_100 base) -------------
__device__ __forceinline__ void hmma(float* c, const uint32_t* a, uint32_t b0, uint32_t b1) {
    asm volatile(
        "mma.sync.aligned.m16n8k16.row.col.f32.bf16.bf16.f32 "
        "{%0,%1,%2,%3}, {%4,%5,%6,%7}, {%8,%9}, {%0,%1,%2,%3};"
        : "+f"(c[0]), "+f"(c[1]), "+f"(c[2]), "+f"(c[3])
        : "r"(a[0]), "r"(a[1]), "r"(a[2]), "r"(a[3]), "r"(b0), "r"(b1));
}

// ---- k0x: x [B][S][D] fp32 -> xt hi/lo bf16 [B][D][S] (transpose+split) ---
__global__ __launch_bounds__(256) void k0_x(const float* __restrict__ x) {
    __shared__ float t[128][65];
    const int s0 = blockIdx.x * 128, b = blockIdx.y;
    const float* xb = x + (size_t)b * S * D;
    for (int i = threadIdx.x; i < 128 * 64; i += 256)
        t[i >> 6][i & 63] = xb[(size_t)(s0 + (i >> 6)) * D + (i & 63)];
    __syncthreads();
    for (int i = threadIdx.x; i < 128 * 64; i += 256) {
        const int d = i >> 7, sl = i & 127;
        const float w = t[sl][d];
        const __nv_bfloat16 h = __float2bfloat16(w);
        const size_t o = ((size_t)b * D + d) * S + s0 + sl;
        g_xth[o] = h;
        g_xtl[o] = __float2bfloat16(w - __bfloat162float(h));
    }
}

// ---- k0w: W_V fp32 -> hi/lo bf16 ------------------------------------------
__global__ __launch_bounds__(256) void k0_wv(const float* __restrict__ WV) {
    const size_t base = ((size_t)blockIdx.x * 256 + threadIdx.x) * 8;
#pragma unroll
    for (int k = 0; k < 8; k++) {
        const float w = WV[base + k];
        const __nv_bfloat16 h = __float2bfloat16(w);
        g_wvh[base + k] = h;
        g_wvl[base + k] = __float2bfloat16(w - __bfloat162float(h));
    }
}

// ---- k1: W_Q'[i,u] = sum_{t>=u} W_Q[i,t]/(t+1) -> hi/lo bf16 --------------
__global__ __launch_bounds__(256) void k1_suffix(const float* __restrict__ WQ) {
    const int row = blockIdx.x, tid = threadIdx.x, base = tid * 8;
    const float* src = WQ + (size_t)row * S;
    float v[8], local = 0.f;
#pragma unroll
    for (int k = 0; k < 8; k++) { v[k] = src[base + k] / (float)(base + k + 1); local += v[k]; }
    float pre = local;
    const int lane = tid & 31, warp = tid >> 5;
#pragma unroll
    for (int off = 1; off < 32; off <<= 1) {
        float n = __shfl_up_sync(0xffffffff, pre, off);
        if (lane >= off) pre += n;
    }
    __shared__ float wsum[8], wpre[8], stot;
    if (lane == 31) wsum[warp] = pre;
    __syncthreads();
    if (tid == 0) {
        float acc = 0.f;
#pragma unroll
        for (int w = 0; w < 8; w++) { wpre[w] = acc; acc += wsum[w]; }
        stot = acc;
    }
    __syncthreads();
    float run = wpre[warp] + (pre - local);
    __nv_bfloat16* dh = g_wqh + (size_t)row * S;
    __nv_bfloat16* dl = g_wql + (size_t)row * S;
#pragma unroll
    for (int k = 0; k < 8; k++) {
        const float w = stot - run;
        run += v[k];
        const __nv_bfloat16 h = __float2bfloat16(w);
        dh[base + k] = h;
        dl[base + k] = __float2bfloat16(w - __bfloat162float(h));
    }
}

// ---- k2: HMMA bf16-split GEMM. A=W' [2048xS], B=xt [256xS] (N=4 batches). -
// grid (32 m-tiles of 64, mat*2+nhalf, 4 kq). 8 warps = 4m x 2n.
// Products hh + hl + lh into fp32 accumulators (lo*lo ~2^-18, dropped).
__global__ __launch_bounds__(256) void k2_hmma() {
    const int mt = blockIdx.x;
    const int mat = blockIdx.y >> 1, nh = blockIdx.y & 1;
    const int kq = blockIdx.z;
    const int wid = threadIdx.x >> 5, lane = threadIdx.x & 31;
    const int wm = wid & 3, wn = wid >> 2;
    const int g = lane >> 2, q2 = (lane & 3) * 2;
    const int m0 = mt * 64 + wm * 16;
    const int nbase = nh * 128 + wn * 64;  // global n in [0,256), n = b*64+d

    const __nv_bfloat16* Ahi = mat ? g_wvh : g_wqh;
    const __nv_bfloat16* Alo = mat ? g_wvl : g_wql;
    const __nv_bfloat16* r0h = Ahi + (size_t)(m0 + g) * S;
    const __nv_bfloat16* r8h = Ahi + (size_t)(m0 + g + 8) * S;
    const __nv_bfloat16* r0l = Alo + (size_t)(m0 + g) * S;
    const __nv_bfloat16* r8l = Alo + (size_t)(m0 + g + 8) * S;

    float acc[8][4];
#pragma unroll
    for (int t = 0; t < 8; t++)
#pragma unroll
        for (int c = 0; c < 4; c++) acc[t][c] = 0.f;

    const int kbeg = kq * 512;
#pragma unroll 1
    for (int ks = 0; ks < 32; ks++) {
        const int kc = kbeg + ks * 16 + q2;
        uint32_t ah[4], al[4];
        ah[0] = *(const uint32_t*)(r0h + kc);
        ah[1] = *(const uint32_t*)(r8h + kc);
        ah[2] = *(const uint32_t*)(r0h + kc + 8);
        ah[3] = *(const uint32_t*)(r8h + kc + 8);
        al[0] = *(const uint32_t*)(r0l + kc);
        al[1] = *(const uint32_t*)(r8l + kc);
        al[2] = *(const uint32_t*)(r0l + kc + 8);
        al[3] = *(const uint32_t*)(r8l + kc + 8);
#pragma unroll
        for (int nt = 0; nt < 8; nt++) {
            const size_t nrow = (size_t)(nbase + nt * 8 + g) * S + kc;
            const uint32_t bh0 = *(const uint32_t*)(g_xth + nrow);
            const uint32_t bh1 = *(const uint32_t*)(g_xth + nrow + 8);
            const uint32_t bl0 = *(const uint32_t*)(g_xtl + nrow);
            const uint32_t bl1 = *(const uint32_t*)(g_xtl + nrow + 8);
            hmma(acc[nt], ah, bh0, bh1);
            hmma(acc[nt], ah, bl0, bl1);
            hmma(acc[nt], al, bh0, bh1);
        }
    }
    // epilogue: c0,c1 -> (row m0+g, cols n0,n0+1); c2,c3 -> row m0+g+8
    float* base = g_k2part + (size_t)(kq * 2 + mat) * B * S * D;
#pragma unroll
    for (int nt = 0; nt < 8; nt++) {
        const int n0 = nbase + nt * 8 + (lane & 3) * 2;
        const int b = n0 >> 6, d = n0 & 63;
        float* p0 = base + (((size_t)b * S + m0 + g) * D + d);
        float* p8 = base + (((size_t)b * S + m0 + g + 8) * D + d);
        *(float2*)p0 = make_float2(acc[nt][0], acc[nt][1]);
        *(float2*)p8 = make_float2(acc[nt][2], acc[nt][3]);
    }
}

// ---- k2r: sum 4 K-quarter partials -> g_Q / g_V ---------------------------
__global__ __launch_bounds__(256) void k2_reduce() {
    const size_t f = (size_t)blockIdx.x * 256 + threadIdx.x;  // float4 index
    const float4* p = (const float4*)g_k2part;
    const size_t stride = (size_t)2 * B * S * D / 4;  // per-kq
    float4 a = p[f];
#pragma unroll
    for (int kq = 1; kq < 4; kq++) {
        float4 q = p[kq * stride + f];
        a.x += q.x; a.y += q.y; a.z += q.z; a.w += q.w;
    }
    const size_t half = (size_t)B * S * D / 4;
    if (f < half) ((float4*)g_Q)[f] = a;
    else ((float4*)g_V)[f - half] = a;
}

// ---- k3: masked scores + fused per-column (m,z) partials ------------------
__global__ __launch_bounds__(256) void k3_scores(const float* __restrict__ x) {
    const int i0 = blockIdx.x * 128, j0 = blockIdx.y * 128, b = blockIdx.z;
    const int tid = threadIdx.x;
    if (i0 + 127 < j0) {  // strictly upper block: sentinel stats, no scores
        if (tid < 128) {
            const size_t o = ((size_t)b * 16 + blockIdx.x) * S + j0 + tid;
            g_partM[o] = -1e38f;
            g_partZ[o] = 0.f;
        }
        return;
    }
    const float* Qb = g_Q + (size_t)b * S * D;
    const float* xb = x + (size_t)b * S * D;
    float* Sc = g_scores + (size_t)b * S * S;
    __shared__ float As[16][132], Bs[16][132];
    const int tx = tid & 15, ty = tid >> 4;
    const int lrow = tid >> 1, lk = (tid & 1) * 8;
    float acc[8][8];
#pragma unroll
    for (int i = 0; i < 8; i++)
#pragma unroll
        for (int j = 0; j < 8; j++) acc[i][j] = 0.f;
#pragma unroll
    for (int kt = 0; kt < D / 16; kt++) {
        const int k0 = kt * 16;
        const float* qp = &Qb[(size_t)(i0 + lrow) * D + k0 + lk];
        float4 q0 = *(const float4*)qp, q1 = *(const float4*)(qp + 4);
        const float* xp = &xb[(size_t)(j0 + lrow) * D + k0 + lk];
        float4 x0 = *(const float4*)xp, x1 = *(const float4*)(xp + 4);
        __syncthreads();
        As[lk + 0][lrow] = q0.x; As[lk + 1][lrow] = q0.y;
        As[lk + 2][lrow] = q0.z; As[lk + 3][lrow] = q0.w;
        As[lk + 4][lrow] = q1.x; As[lk + 5][lrow] = q1.y;
        As[lk + 6][lrow] = q1.z; As[lk + 7][lrow] = q1.w;
        Bs[lk + 0][lrow] = x0.x; Bs[lk + 1][lrow] = x0.y;
        Bs[lk + 2][lrow] = x0.z; Bs[lk + 3][lrow] = x0.w;
        Bs[lk + 4][lrow] = x1.x; Bs[lk + 5][lrow] = x1.y;
        Bs[lk + 6][lrow] = x1.z; Bs[lk + 7][lrow] = x1.w;
        __syncthreads();
#pragma unroll
        for (int k = 0; k < 16; k++) {
            float4 a0 = *(const float4*)&As[k][ty * 8];
            float4 a1 = *(const float4*)&As[k][ty * 8 + 4];
            float4 b0 = *(const float4*)&Bs[k][tx * 4];
            float4 b1 = *(const float4*)&Bs[k][64 + tx * 4];
            float av[8] = {a0.x, a0.y, a0.z, a0.w, a1.x, a1.y, a1.z, a1.w};
            float bv[8] = {b0.x, b0.y, b0.z, b0.w, b1.x, b1.y, b1.z, b1.w};
#pragma unroll
            for (int i = 0; i < 8; i++)
#pragma unroll
                for (int j = 0; j < 8; j++) acc[i][j] = fmaf(av[i], bv[j], acc[i][j]);
        }
        __syncthreads();
    }
    float mcol[8];
#pragma unroll
    for (int c = 0; c < 8; c++) mcol[c] = -1e38f;
    float sc[8][8];
#pragma unroll
    for (int r = 0; r < 8; r++) {
        const int gi = i0 + ty * 8 + r;
#pragma unroll
        for (int c = 0; c < 8; c++) {
            const int gj = j0 + ((c < 4) ? tx * 4 + c : 64 + tx * 4 + (c - 4));
            const float v = acc[r][c];
            const float o = (gi >= gj && v > 1.0f) ? v : NEGBIG;
            acc[r][c] = o;
            const float s = o * SCALE;
            sc[r][c] = s;
            mcol[c] = fmaxf(mcol[c], s);
        }
    }
    float zcol[8];
#pragma unroll
    for (int c = 0; c < 8; c++) zcol[c] = 0.f;
#pragma unroll
    for (int r = 0; r < 8; r++) {
        const int gi = i0 + ty * 8 + r;
        float* sp = &Sc[(size_t)gi * S + j0];
        *(float4*)&sp[tx * 4] = make_float4(acc[r][0], acc[r][1], acc[r][2], acc[r][3]);
        *(float4*)&sp[64 + tx * 4] = make_float4(acc[r][4], acc[r][5], acc[r][6], acc[r][7]);
#pragma unroll
        for (int c = 0; c < 8; c++) zcol[c] += __expf(sc[r][c] - mcol[c]);
    }
    __syncthreads();
    float* red_m = &As[0][0];
    float* red_z = &Bs[0][0];
#pragma unroll
    for (int c = 0; c < 8; c++) {
        const int col = (c < 4) ? (tx * 4 + c) : (64 + tx * 4 + c - 4);
        red_m[ty * 128 + col] = mcol[c];
        red_z[ty * 128 + col] = zcol[c];
    }
    __syncthreads();
    if (tid < 128) {
        float m = -1e38f;
#pragma unroll
        for (int t = 0; t < 16; t++) m = fmaxf(m, red_m[t * 128 + tid]);
        float z = 0.f;
#pragma unroll
        for (int t = 0; t < 16; t++) z += red_z[t * 128 + tid] * __expf(red_m[t * 128 + tid] - m);
        const size_t o = ((size_t)b * 16 + blockIdx.x) * S + j0 + tid;
        g_partM[o] = m;
        g_partZ[o] = z;
    }
}

// ---- k4b: reduce 16 partials -> colC[j] = m_j + log(z_j) ------------------
__global__ __launch_bounds__(256) void k4b_reduce() {
    const int j = blockIdx.x * 256 + threadIdx.x, b = blockIdx.y;
    float pm[16], pz[16];
#pragma unroll
    for (int i = 0; i < 16; i++) {
        pm[i] = g_partM[((size_t)b * 16 + i) * S + j];
        pz[i] = g_partZ[((size_t)b * 16 + i) * S + j];
    }
    float m = -1e38f;
#pragma unroll
    for (int i = 0; i < 16; i++) m = fmaxf(m, pm[i]);
    float z = 0.f;
#pragma unroll
    for (int i = 0; i < 16; i++) z += pz[i] * __expf(pm[i] - m);
    g_colC[b * S + j] = m + logf(z);
}

// ---- k5: partial out = exp(s*scale - colC_j) @ V, split-K over j-tiles ----
__global__ __launch_bounds__(256) void k5_pv() {
    const int mb = blockIdx.x, sp = blockIdx.y, b = blockIdx.z;
    const int i0 = mb * 128;
    const float* Sc = g_scores + (size_t)b * S * S;
    const float* Vb = g_V + (size_t)b * S * D;
    const float* cC = g_colC + b * S;
    float* P = g_part + (size_t)(sp * B + b) * S * D;
    __shared__ float As[16][132];
    __shared__ float Bs[16][64];
    const int tid = threadIdx.x, tx = tid & 7, ty = tid >> 3;
    const int arow = tid >> 1, akq = (tid & 1) * 8;
    const int bk = tid >> 4, bd = (tid & 15) * 4;
    float acc[4][8];
#pragma unroll
    for (int i = 0; i < 4; i++)
#pragma unroll
        for (int j = 0; j < 8; j++) acc[i][j] = 0.f;
    for (int t = sp; t <= mb; t += KS) {
#pragma unroll 1
        for (int kk = 0; kk < 8; kk++) {
            const int k0 = t * 128 + kk * 16;
            const float* ap = &Sc[(size_t)(i0 + arow) * S + k0 + akq];
            float4 a0 = *(const float4*)ap, a1 = *(const float4*)(ap + 4);
            float4 c0 = *(const float4*)&cC[k0 + akq];
            float4 c1 = *(const float4*)&cC[k0 + akq + 4];
            float4 vb = *(const float4*)&Vb[(size_t)(k0 + bk) * D + bd];
            __syncthreads();
            As[akq + 0][arow] = __expf(fmaf(a0.x, SCALE, -c0.x));
            As[akq + 1][arow] = __expf(fmaf(a0.y, SCALE, -c0.y));
            As[akq + 2][arow] = __expf(fmaf(a0.z, SCALE, -c0.z));
            As[akq + 3][arow] = __expf(fmaf(a0.w, SCALE, -c0.w));
            As[akq + 4][arow] = __expf(fmaf(a1.x, SCALE, -c1.x));
            As[akq + 5][arow] = __expf(fmaf(a1.y, SCALE, -c1.y));
            As[akq + 6][arow] = __expf(fmaf(a1.z, SCALE, -c1.z));
            As[akq + 7][arow] = __expf(fmaf(a1.w, SCALE, -c1.w));
            *(float4*)&Bs[bk][bd] = vb;
            __syncthreads();
#pragma unroll
            for (int k = 0; k < 16; k++) {
                float4 a4 = *(const float4*)&As[k][ty * 4];
                float4 b0 = *(const float4*)&Bs[k][tx * 4];
                float4 b1 = *(const float4*)&Bs[k][32 + tx * 4];
                float av[4] = {a4.x, a4.y, a4.z, a4.w};
                float bv[8] = {b0.x, b0.y, b0.z, b0.w, b1.x, b1.y, b1.z, b1.w};
#pragma unroll
                for (int i = 0; i < 4; i++)
#pragma unroll
                    for (int j = 0; j < 8; j++) acc[i][j] = fmaf(av[i], bv[j], acc[i][j]);
            }
        }
    }
#pragma unroll
    for (int i = 0; i < 4; i++) {
        float* o = &P[(size_t)(i0 + ty * 4 + i) * D];
        *(float4*)&o[tx * 4] = make_float4(acc[i][0], acc[i][1], acc[i][2], acc[i][3]);
        *(float4*)&o[32 + tx * 4] = make_float4(acc[i][4], acc[i][5], acc[i][6], acc[i][7]);
    }
}

// ---- k6: reduce KS split-K partials into d_out ----------------------------
__global__ __launch_bounds__(256) void k6_reduce(float* __restrict__ out) {
    const int idx = blockIdx.x * 256 + threadIdx.x;
    const float4* p = (const float4*)g_part;
    const size_t n4 = (size_t)B * S * D / 4;
    float4 a = p[idx];
#pragma unroll
    for (int sp = 1; sp < KS; sp++) {
        float4 q = p[sp * n4 + idx];
        a.x += q.x; a.y += q.y; a.z += q.z; a.w += q.w;
    }
    ((float4*)out)[idx] = a;
}

extern "C" void kernel_launch(void* const* d_in, const int* in_sizes, int n_in,
                              void* d_out, int out_size) {
    int xi = 0;
    for (int i = 0; i < n_in; i++)
        if (in_sizes[i] == B * S * D) { xi = i; break; }
    int o1 = -1, o2 = -1;
    for (int i = 0; i < n_in; i++)
        if (i != xi) { if (o1 < 0) o1 = i; else o2 = i; }
    const float* x = (const float*)d_in[xi];
    const float* WQ = (const float*)d_in[o1];
    const float* WV = (const float*)d_in[o2];

    k0_x<<<dim3(S / 128, B), 256>>>(x);
    k0_wv<<<(S * S) / (256 * 8), 256>>>(WV);
    k1_suffix<<<S, 256>>>(WQ);
    k2_hmma<<<dim3(32, 4, 4), 256>>>();
    k2_reduce<<<(2 * B * S * D / 4) / 256, 256>>>();
    k3_scores<<<dim3(16, 16, B), 256>>>(x);
    k4b_reduce<<<dim3(S / 256, B), 256>>>();
    k5_pv<<<dim3(16, KS, B), 256>>>();
    k6_reduce<<<(B * S * D / 4) / 256, 256>>>((float*)d_out);
}

// round 12
// speedup vs baseline: 1.7753x; 1.7753x over previous
#include <cuda_runtime.h>
#include <cuda_bf16.h>
#include <cstdint>

namespace {
constexpr int B = 4, S = 2048, D = 64, KS = 8;
constexpr int MF = S / 16, KF = S / 16, NF = (B * D) / 8;  // 128, 128, 32
constexpr float SCALE = 0.022097086912079612f;  // 1/sqrt(2048)
constexpr float NEGBIG = -3.402823466e38f;
}

// ---- fragment-linear scratch: frag[(mf*KF+kf)*32 + lane] = uint4 ----------
__device__ uint4 g_faq_h[(size_t)MF * KF * 32];  // W_Q' hi  (a0,a1,a2,a3)
__device__ uint4 g_faq_l[(size_t)MF * KF * 32];  // W_Q' lo
__device__ uint4 g_fav_h[(size_t)MF * KF * 32];  // W_V  hi
__device__ uint4 g_fav_l[(size_t)MF * KF * 32];  // W_V  lo
__device__ uint4 g_fbx[(size_t)NF * KF * 32];    // x: (bh0,bh1,bl0,bl1)
__device__ float g_k2part[(size_t)4 * 2 * B * S * D];  // [kq][mat][b][s][d]
__device__ float g_Q[(size_t)B * S * D];
__device__ float g_V[(size_t)B * S * D];
__device__ float g_scores[(size_t)B * S * S];
__device__ float g_partM[B * 16 * S];
__device__ float g_partZ[B * 16 * S];
__device__ float g_colC[B * S];
__device__ float g_part[(size_t)KS * B * S * D];

// ---- helpers ---------------------------------------------------------------
__device__ __forceinline__ void hmma(float* c, const uint32_t* a, uint32_t b0, uint32_t b1) {
    asm volatile(
        "mma.sync.aligned.m16n8k16.row.col.f32.bf16.bf16.f32 "
        "{%0,%1,%2,%3}, {%4,%5,%6,%7}, {%8,%9}, {%0,%1,%2,%3};"
        : "+f"(c[0]), "+f"(c[1]), "+f"(c[2]), "+f"(c[3])
        : "r"(a[0]), "r"(a[1]), "r"(a[2]), "r"(a[3]), "r"(b0), "r"(b1));
}
__device__ __forceinline__ uint32_t bpack(__nv_bfloat16 e, __nv_bfloat16 o) {
    return (uint32_t)__bfloat16_as_ushort(e) | ((uint32_t)__bfloat16_as_ushort(o) << 16);
}
__device__ __forceinline__ void bsplit(float v, __nv_bfloat16& h, __nv_bfloat16& l) {
    h = __float2bfloat16(v);
    l = __float2bfloat16(v - __bfloat162float(h));
}

// writes one row's 8 consecutive-k fp32 values into A-frag layout (hi+lo)
__device__ __forceinline__ void write_a_frags(const float* wv, int row, int tid,
                                              uint32_t* outh, uint32_t* outl) {
    const int mf = row >> 4, g = row & 7;
    const int reg = (((row & 15) < 8) ? 0 : 1) + ((tid & 1) ? 2 : 0);
    const int kf = tid >> 1;
    __nv_bfloat16 h[8], l[8];
#pragma unroll
    for (int j = 0; j < 8; j++) bsplit(wv[j], h[j], l[j]);
#pragma unroll
    for (int q = 0; q < 4; q++) {
        const size_t idx = (((size_t)mf * KF + kf) * 32 + g * 4 + q) * 4 + reg;
        outh[idx] = bpack(h[2 * q], h[2 * q + 1]);
        outl[idx] = bpack(l[2 * q], l[2 * q + 1]);
    }
}

// ---- k0x: x [B][S][D] -> B-frag layout (n = b*64+d, k = s) -----------------
__global__ __launch_bounds__(256) void k0_x(const float* __restrict__ x) {
    __shared__ float t[128][65];
    const int s0 = blockIdx.x * 128, b = blockIdx.y;
    const float* xb = x + (size_t)b * S * D;
    for (int i = threadIdx.x; i < 128 * 64; i += 256)
        t[i >> 6][i & 63] = xb[(size_t)(s0 + (i >> 6)) * D + (i & 63)];
    __syncthreads();
    const int w = threadIdx.x >> 5, lane = threadIdx.x & 31;
    const int g = lane >> 2, q = lane & 3;
    const int nf = b * 8 + w, d = w * 8 + g;
#pragma unroll
    for (int kfl = 0; kfl < 8; kfl++) {
        const int sb = kfl * 16;
        __nv_bfloat16 h0, l0, h1, l1, h2, l2, h3, l3;
        bsplit(t[sb + 2 * q][d], h0, l0);
        bsplit(t[sb + 2 * q + 1][d], h1, l1);
        bsplit(t[sb + 8 + 2 * q][d], h2, l2);
        bsplit(t[sb + 9 + 2 * q][d], h3, l3);
        uint4 v;
        v.x = bpack(h0, h1);  // bh0: k-lo
        v.y = bpack(h2, h3);  // bh1: k-hi
        v.z = bpack(l0, l1);  // bl0
        v.w = bpack(l2, l3);  // bl1
        g_fbx[((size_t)nf * KF + (s0 >> 4) + kfl) * 32 + lane] = v;
    }
}

// ---- k0w: W_V -> A-frag layout (one block per row) -------------------------
__global__ __launch_bounds__(256) void k0_wv(const float* __restrict__ WV) {
    const int row = blockIdx.x, tid = threadIdx.x;
    const float* src = WV + (size_t)row * S + tid * 8;
    float wv[8];
#pragma unroll
    for (int j = 0; j < 8; j++) wv[j] = src[j];
    write_a_frags(wv, row, tid, (uint32_t*)g_fav_h, (uint32_t*)g_fav_l);
}

// ---- k1: W_Q'[i,u] = sum_{t>=u} W_Q[i,t]/(t+1) -> A-frag layout ------------
__global__ __launch_bounds__(256) void k1_suffix(const float* __restrict__ WQ) {
    const int row = blockIdx.x, tid = threadIdx.x, base = tid * 8;
    const float* src = WQ + (size_t)row * S;
    float v[8], local = 0.f;
#pragma unroll
    for (int k = 0; k < 8; k++) { v[k] = src[base + k] / (float)(base + k + 1); local += v[k]; }
    float pre = local;
    const int lane = tid & 31, warp = tid >> 5;
#pragma unroll
    for (int off = 1; off < 32; off <<= 1) {
        float n = __shfl_up_sync(0xffffffff, pre, off);
        if (lane >= off) pre += n;
    }
    __shared__ float wsum[8], wpre[8], stot;
    if (lane == 31) wsum[warp] = pre;
    __syncthreads();
    if (tid == 0) {
        float acc = 0.f;
#pragma unroll
        for (int w = 0; w < 8; w++) { wpre[w] = acc; acc += wsum[w]; }
        stot = acc;
    }
    __syncthreads();
    float run = wpre[warp] + (pre - local);
    float wv[8];
#pragma unroll
    for (int k = 0; k < 8; k++) { wv[k] = stot - run; run += v[k]; }
    write_a_frags(wv, row, tid, (uint32_t*)g_faq_h, (uint32_t*)g_faq_l);
}

// ---- k2: HMMA GEMM on fragment-linear operands -----------------------------
// grid (32 m-tiles of 64, mat*2+nhalf, 4 kq). 8 warps = 4m x 2n.
__global__ __launch_bounds__(256) void k2_hmma() {
    const int mt = blockIdx.x;
    const int mat = blockIdx.y >> 1, nh = blockIdx.y & 1;
    const int kq = blockIdx.z;
    const int wid = threadIdx.x >> 5, lane = threadIdx.x & 31;
    const int wm = wid & 3, wn = wid >> 2;
    const int mf = mt * 4 + wm;
    const int nfb = nh * 16 + wn * 8;

    const uint4* Ah = (mat ? g_fav_h : g_faq_h) + ((size_t)mf * KF + kq * 32) * 32 + lane;
    const uint4* Al = (mat ? g_fav_l : g_faq_l) + ((size_t)mf * KF + kq * 32) * 32 + lane;
    const uint4* Bp[8];
#pragma unroll
    for (int nt = 0; nt < 8; nt++)
        Bp[nt] = g_fbx + ((size_t)(nfb + nt) * KF + kq * 32) * 32 + lane;

    float acc[8][4];
#pragma unroll
    for (int t = 0; t < 8; t++)
#pragma unroll
        for (int c = 0; c < 4; c++) acc[t][c] = 0.f;

#pragma unroll 4
    for (int ks = 0; ks < 32; ks++) {
        const uint4 av = Ah[ks * 32];
        const uint4 lv = Al[ks * 32];
        const uint32_t ah[4] = {av.x, av.y, av.z, av.w};
        const uint32_t al[4] = {lv.x, lv.y, lv.z, lv.w};
#pragma unroll
        for (int nt = 0; nt < 8; nt++) {
            const uint4 bb = Bp[nt][ks * 32];
            hmma(acc[nt], ah, bb.x, bb.y);  // hi*hi
            hmma(acc[nt], ah, bb.z, bb.w);  // hi*lo
            hmma(acc[nt], al, bb.x, bb.y);  // lo*hi
        }
    }
    // epilogue (layout verified in round 11)
    const int g = lane >> 2;
    const int m0 = mf * 16;
    float* base = g_k2part + (size_t)(kq * 2 + mat) * B * S * D;
#pragma unroll
    for (int nt = 0; nt < 8; nt++) {
        const int n0 = (nfb + nt) * 8 + (lane & 3) * 2;
        const int b = n0 >> 6, d = n0 & 63;
        float* p0 = base + (((size_t)b * S + m0 + g) * D + d);
        float* p8 = base + (((size_t)b * S + m0 + g + 8) * D + d);
        *(float2*)p0 = make_float2(acc[nt][0], acc[nt][1]);
        *(float2*)p8 = make_float2(acc[nt][2], acc[nt][3]);
    }
}

// ---- k2r: sum 4 K-quarter partials -> g_Q / g_V ----------------------------
__global__ __launch_bounds__(256) void k2_reduce() {
    const size_t f = (size_t)blockIdx.x * 256 + threadIdx.x;  // float4 index
    const float4* p = (const float4*)g_k2part;
    const size_t stride = (size_t)2 * B * S * D / 4;
    float4 a = p[f];
#pragma unroll
    for (int kq = 1; kq < 4; kq++) {
        float4 q = p[kq * stride + f];
        a.x += q.x; a.y += q.y; a.z += q.z; a.w += q.w;
    }
    const size_t half = (size_t)B * S * D / 4;
    if (f < half) ((float4*)g_Q)[f] = a;
    else ((float4*)g_V)[f - half] = a;
}

// ---- k3: masked scores + fused per-column (m,z) partials -------------------
__global__ __launch_bounds__(256) void k3_scores(const float* __restrict__ x) {
    const int i0 = blockIdx.x * 128, j0 = blockIdx.y * 128, b = blockIdx.z;
    const int tid = threadIdx.x;
    if (i0 + 127 < j0) {
        if (tid < 128) {
            const size_t o = ((size_t)b * 16 + blockIdx.x) * S + j0 + tid;
            g_partM[o] = -1e38f;
            g_partZ[o] = 0.f;
        }
        return;
    }
    const float* Qb = g_Q + (size_t)b * S * D;
    const float* xb = x + (size_t)b * S * D;
    float* Sc = g_scores + (size_t)b * S * S;
    __shared__ float As[16][132], Bs[16][132];
    const int tx = tid & 15, ty = tid >> 4;
    const int lrow = tid >> 1, lk = (tid & 1) * 8;
    float acc[8][8];
#pragma unroll
    for (int i = 0; i < 8; i++)
#pragma unroll
        for (int j = 0; j < 8; j++) acc[i][j] = 0.f;
#pragma unroll
    for (int kt = 0; kt < D / 16; kt++) {
        const int k0 = kt * 16;
        const float* qp = &Qb[(size_t)(i0 + lrow) * D + k0 + lk];
        float4 q0 = *(const float4*)qp, q1 = *(const float4*)(qp + 4);
        const float* xp = &xb[(size_t)(j0 + lrow) * D + k0 + lk];
        float4 x0 = *(const float4*)xp, x1 = *(const float4*)(xp + 4);
        __syncthreads();
        As[lk + 0][lrow] = q0.x; As[lk + 1][lrow] = q0.y;
        As[lk + 2][lrow] = q0.z; As[lk + 3][lrow] = q0.w;
        As[lk + 4][lrow] = q1.x; As[lk + 5][lrow] = q1.y;
        As[lk + 6][lrow] = q1.z; As[lk + 7][lrow] = q1.w;
        Bs[lk + 0][lrow] = x0.x; Bs[lk + 1][lrow] = x0.y;
        Bs[lk + 2][lrow] = x0.z; Bs[lk + 3][lrow] = x0.w;
        Bs[lk + 4][lrow] = x1.x; Bs[lk + 5][lrow] = x1.y;
        Bs[lk + 6][lrow] = x1.z; Bs[lk + 7][lrow] = x1.w;
        __syncthreads();
#pragma unroll
        for (int k = 0; k < 16; k++) {
            float4 a0 = *(const float4*)&As[k][ty * 8];
            float4 a1 = *(const float4*)&As[k][ty * 8 + 4];
            float4 b0 = *(const float4*)&Bs[k][tx * 4];
            float4 b1 = *(const float4*)&Bs[k][64 + tx * 4];
            float av[8] = {a0.x, a0.y, a0.z, a0.w, a1.x, a1.y, a1.z, a1.w};
            float bv[8] = {b0.x, b0.y, b0.z, b0.w, b1.x, b1.y, b1.z, b1.w};
#pragma unroll
            for (int i = 0; i < 8; i++)
#pragma unroll
                for (int j = 0; j < 8; j++) acc[i][j] = fmaf(av[i], bv[j], acc[i][j]);
        }
        __syncthreads();
    }
    float mcol[8];
#pragma unroll
    for (int c = 0; c < 8; c++) mcol[c] = -1e38f;
    float sc[8][8];
#pragma unroll
    for (int r = 0; r < 8; r++) {
        const int gi = i0 + ty * 8 + r;
#pragma unroll
        for (int c = 0; c < 8; c++) {
            const int gj = j0 + ((c < 4) ? tx * 4 + c : 64 + tx * 4 + (c - 4));
            const float v = acc[r][c];
            const float o = (gi >= gj && v > 1.0f) ? v : NEGBIG;
            acc[r][c] = o;
            const float s = o * SCALE;
            sc[r][c] = s;
            mcol[c] = fmaxf(mcol[c], s);
        }
    }
    float zcol[8];
#pragma unroll
    for (int c = 0; c < 8; c++) zcol[c] = 0.f;
#pragma unroll
    for (int r = 0; r < 8; r++) {
        const int gi = i0 + ty * 8 + r;
        float* sp = &Sc[(size_t)gi * S + j0];
        *(float4*)&sp[tx * 4] = make_float4(acc[r][0], acc[r][1], acc[r][2], acc[r][3]);
        *(float4*)&sp[64 + tx * 4] = make_float4(acc[r][4], acc[r][5], acc[r][6], acc[r][7]);
#pragma unroll
        for (int c = 0; c < 8; c++) zcol[c] += __expf(sc[r][c] - mcol[c]);
    }
    __syncthreads();
    float* red_m = &As[0][0];
    float* red_z = &Bs[0][0];
#pragma unroll
    for (int c = 0; c < 8; c++) {
        const int col = (c < 4) ? (tx * 4 + c) : (64 + tx * 4 + c - 4);
        red_m[ty * 128 + col] = mcol[c];
        red_z[ty * 128 + col] = zcol[c];
    }
    __syncthreads();
    if (tid < 128) {
        float m = -1e38f;
#pragma unroll
        for (int t = 0; t < 16; t++) m = fmaxf(m, red_m[t * 128 + tid]);
        float z = 0.f;
#pragma unroll
        for (int t = 0; t < 16; t++) z += red_z[t * 128 + tid] * __expf(red_m[t * 128 + tid] - m);
        const size_t o = ((size_t)b * 16 + blockIdx.x) * S + j0 + tid;
        g_partM[o] = m;
        g_partZ[o] = z;
    }
}

// ---- k4b: reduce 16 partials -> colC[j] = m_j + log(z_j) -------------------
__global__ __launch_bounds__(256) void k4b_reduce() {
    const int j = blockIdx.x * 256 + threadIdx.x, b = blockIdx.y;
    float pm[16], pz[16];
#pragma unroll
    for (int i = 0; i < 16; i++) {
        pm[i] = g_partM[((size_t)b * 16 + i) * S + j];
        pz[i] = g_partZ[((size_t)b * 16 + i) * S + j];
    }
    float m = -1e38f;
#pragma unroll
    for (int i = 0; i < 16; i++) m = fmaxf(m, pm[i]);
    float z = 0.f;
#pragma unroll
    for (int i = 0; i < 16; i++) z += pz[i] * __expf(pm[i] - m);
    g_colC[b * S + j] = m + logf(z);
}

// ---- k5: partial out = exp(s*scale - colC_j) @ V, split-K over j-tiles -----
__global__ __launch_bounds__(256) void k5_pv() {
    const int mb = blockIdx.x, sp = blockIdx.y, b = blockIdx.z;
    const int i0 = mb * 128;
    const float* Sc = g_scores + (size_t)b * S * S;
    const float* Vb = g_V + (size_t)b * S * D;
    const float* cC = g_colC + b * S;
    float* P = g_part + (size_t)(sp * B + b) * S * D;
    __shared__ float As[16][132];
    __shared__ float Bs[16][64];
    const int tid = threadIdx.x, tx = tid & 7, ty = tid >> 3;
    const int arow = tid >> 1, akq = (tid & 1) * 8;
    const int bk = tid >> 4, bd = (tid & 15) * 4;
    float acc[4][8];
#pragma unroll
    for (int i = 0; i < 4; i++)
#pragma unroll
        for (int j = 0; j < 8; j++) acc[i][j] = 0.f;
    for (int t = sp; t <= mb; t += KS) {
#pragma unroll 1
        for (int kk = 0; kk < 8; kk++) {
            const int k0 = t * 128 + kk * 16;
            const float* ap = &Sc[(size_t)(i0 + arow) * S + k0 + akq];
            float4 a0 = *(const float4*)ap, a1 = *(const float4*)(ap + 4);
            float4 c0 = *(const float4*)&cC[k0 + akq];
            float4 c1 = *(const float4*)&cC[k0 + akq + 4];
            float4 vb = *(const float4*)&Vb[(size_t)(k0 + bk) * D + bd];
            __syncthreads();
            As[akq + 0][arow] = __expf(fmaf(a0.x, SCALE, -c0.x));
            As[akq + 1][arow] = __expf(fmaf(a0.y, SCALE, -c0.y));
            As[akq + 2][arow] = __expf(fmaf(a0.z, SCALE, -c0.z));
            As[akq + 3][arow] = __expf(fmaf(a0.w, SCALE, -c0.w));
            As[akq + 4][arow] = __expf(fmaf(a1.x, SCALE, -c1.x));
            As[akq + 5][arow] = __expf(fmaf(a1.y, SCALE, -c1.y));
            As[akq + 6][arow] = __expf(fmaf(a1.z, SCALE, -c1.z));
            As[akq + 7][arow] = __expf(fmaf(a1.w, SCALE, -c1.w));
            *(float4*)&Bs[bk][bd] = vb;
            __syncthreads();
#pragma unroll
            for (int k = 0; k < 16; k++) {
                float4 a4 = *(const float4*)&As[k][ty * 4];
                float4 b0 = *(const float4*)&Bs[k][tx * 4];
                float4 b1 = *(const float4*)&Bs[k][32 + tx * 4];
                float av[4] = {a4.x, a4.y, a4.z, a4.w};
                float bv[8] = {b0.x, b0.y, b0.z, b0.w, b1.x, b1.y, b1.z, b1.w};
#pragma unroll
                for (int i = 0; i < 4; i++)
#pragma unroll
                    for (int j = 0; j < 8; j++) acc[i][j] = fmaf(av[i], bv[j], acc[i][j]);
            }
        }
    }
#pragma unroll
    for (int i = 0; i < 4; i++) {
        float* o = &P[(size_t)(i0 + ty * 4 + i) * D];
        *(float4*)&o[tx * 4] = make_float4(acc[i][0], acc[i][1], acc[i][2], acc[i][3]);
        *(float4*)&o[32 + tx * 4] = make_float4(acc[i][4], acc[i][5], acc[i][6], acc[i][7]);
    }
}

// ---- k6: reduce KS split-K partials into d_out -----------------------------
__global__ __launch_bounds__(256) void k6_reduce(float* __restrict__ out) {
    const int idx = blockIdx.x * 256 + threadIdx.x;
    const float4* p = (const float4*)g_part;
    const size_t n4 = (size_t)B * S * D / 4;
    float4 a = p[idx];
#pragma unroll
    for (int sp = 1; sp < KS; sp++) {
        float4 q = p[sp * n4 + idx];
        a.x += q.x; a.y += q.y; a.z += q.z; a.w += q.w;
    }
    ((float4*)out)[idx] = a;
}

extern "C" void kernel_launch(void* const* d_in, const int* in_sizes, int n_in,
                              void* d_out, int out_size) {
    int xi = 0;
    for (int i = 0; i < n_in; i++)
        if (in_sizes[i] == B * S * D) { xi = i; break; }
    int o1 = -1, o2 = -1;
    for (int i = 0; i < n_in; i++)
        if (i != xi) { if (o1 < 0) o1 = i; else o2 = i; }
    const float* x = (const float*)d_in[xi];
    const float* WQ = (const float*)d_in[o1];
    const float* WV = (const float*)d_in[o2];

    k0_x<<<dim3(S / 128, B), 256>>>(x);
    k0_wv<<<S, 256>>>(WV);
    k1_suffix<<<S, 256>>>(WQ);
    k2_hmma<<<dim3(32, 4, 4), 256>>>();
    k2_reduce<<<(2 * B * S * D / 4) / 256, 256>>>();
    k3_scores<<<dim3(16, 16, B), 256>>>(x);
    k4b_reduce<<<dim3(S / 256, B), 256>>>();
    k5_pv<<<dim3(16, KS, B), 256>>>();
    k6_reduce<<<(B * S * D / 4) / 256, 256>>>((float*)d_out);
}

// round 13
// speedup vs baseline: 1.9974x; 1.1251x over previous
#include <cuda_runtime.h>
#include <cuda_bf16.h>
#include <cstdint>

namespace {
constexpr int B = 4, S = 2048, D = 64, KS = 8;
constexpr int MF = S / 16, KF = S / 16, NF = (B * D) / 8;  // 128, 128, 32
constexpr float SCALE = 0.022097086912079612f;  // 1/sqrt(2048)
constexpr float NEGBIG = -3.402823466e38f;
}

// ---- fragment-linear scratch: frag[(mf*KF+kf)*32 + lane] = uint4 ----------
__device__ uint4 g_faq_h[(size_t)MF * KF * 32];  // W_Q' hi  (a0,a1,a2,a3)
__device__ uint4 g_faq_l[(size_t)MF * KF * 32];  // W_Q' lo
__device__ uint4 g_fav_h[(size_t)MF * KF * 32];  // W_V  hi
__device__ uint4 g_fav_l[(size_t)MF * KF * 32];  // W_V  lo
__device__ uint4 g_fbx[(size_t)NF * KF * 32];    // x (k=s): (bh0,bh1,bl0,bl1)
// k3 fragments: Q as A-frags (k=d), x as B-frags (n=j, k=d)
__device__ uint4 g_fq3h[(size_t)B * 128 * 4 * 32];
__device__ uint4 g_fq3l[(size_t)B * 128 * 4 * 32];
__device__ uint4 g_fx3[(size_t)B * 256 * 4 * 32];
__device__ float g_k2part[(size_t)4 * 2 * B * S * D];  // [kq][mat][b][s][d]
__device__ float g_Q[(size_t)B * S * D];
__device__ float g_V[(size_t)B * S * D];
__device__ float g_scores[(size_t)B * S * S];
__device__ float g_partM[B * 16 * S];
__device__ float g_partZ[B * 16 * S];
__device__ float g_colC[B * S];
__device__ float g_part[(size_t)KS * B * S * D];

// ---- helpers ---------------------------------------------------------------
__device__ __forceinline__ void hmma(float* c, const uint32_t* a, uint32_t b0, uint32_t b1) {
    asm volatile(
        "mma.sync.aligned.m16n8k16.row.col.f32.bf16.bf16.f32 "
        "{%0,%1,%2,%3}, {%4,%5,%6,%7}, {%8,%9}, {%0,%1,%2,%3};"
        : "+f"(c[0]), "+f"(c[1]), "+f"(c[2]), "+f"(c[3])
        : "r"(a[0]), "r"(a[1]), "r"(a[2]), "r"(a[3]), "r"(b0), "r"(b1));
}
__device__ __forceinline__ uint32_t bpack(__nv_bfloat16 e, __nv_bfloat16 o) {
    return (uint32_t)__bfloat16_as_ushort(e) | ((uint32_t)__bfloat16_as_ushort(o) << 16);
}
__device__ __forceinline__ void bsplit(float v, __nv_bfloat16& h, __nv_bfloat16& l) {
    h = __float2bfloat16(v);
    l = __float2bfloat16(v - __bfloat162float(h));
}
__device__ __forceinline__ uint32_t packhi2(float a, float b) {
    __nv_bfloat16 ha, la, hb, lb;
    bsplit(a, ha, la); bsplit(b, hb, lb);
    return bpack(ha, hb);
}
__device__ __forceinline__ void pack2hl(float a, float b, uint32_t& hi, uint32_t& lo) {
    __nv_bfloat16 ha, la, hb, lb;
    bsplit(a, ha, la); bsplit(b, hb, lb);
    hi = bpack(ha, hb); lo = bpack(la, lb);
}

// writes one row's 8 consecutive-k fp32 values into A-frag layout (hi+lo)
__device__ __forceinline__ void write_a_frags(const float* wv, int row, int tid,
                                              uint32_t* outh, uint32_t* outl) {
    const int mf = row >> 4, g = row & 7;
    const int reg = (((row & 15) < 8) ? 0 : 1) + ((tid & 1) ? 2 : 0);
    const int kf = tid >> 1;
    __nv_bfloat16 h[8], l[8];
#pragma unroll
    for (int j = 0; j < 8; j++) bsplit(wv[j], h[j], l[j]);
#pragma unroll
    for (int q = 0; q < 4; q++) {
        const size_t idx = (((size_t)mf * KF + kf) * 32 + g * 4 + q) * 4 + reg;
        outh[idx] = bpack(h[2 * q], h[2 * q + 1]);
        outl[idx] = bpack(l[2 * q], l[2 * q + 1]);
    }
}

// ---- k0x: x -> k2 B-frags (k=s) AND k3 B-frags (n=j, k=d) ------------------
__global__ __launch_bounds__(256) void k0_x(const float* __restrict__ x) {
    __shared__ float t[128][65];
    const int s0 = blockIdx.x * 128, b = blockIdx.y;
    const float* xb = x + (size_t)b * S * D;
    for (int i = threadIdx.x; i < 128 * 64; i += 256)
        t[i >> 6][i & 63] = xb[(size_t)(s0 + (i >> 6)) * D + (i & 63)];
    __syncthreads();
    const int w = threadIdx.x >> 5, lane = threadIdx.x & 31;
    const int g = lane >> 2, q = lane & 3;
    {   // k2 B-frags: n = b*64+d, k = s
        const int nf = b * 8 + w, d = w * 8 + g;
#pragma unroll
        for (int kfl = 0; kfl < 8; kfl++) {
            const int sb = kfl * 16;
            uint4 v;
            pack2hl(t[sb + 2 * q][d], t[sb + 2 * q + 1][d], v.x, v.z);
            pack2hl(t[sb + 8 + 2 * q][d], t[sb + 9 + 2 * q][d], v.y, v.w);
            g_fbx[((size_t)nf * KF + (s0 >> 4) + kfl) * 32 + lane] = v;
        }
    }
    // k3 B-frags: n = j (seq), k = d. warp handles 2 nf.
#pragma unroll
    for (int r = 0; r < 2; r++) {
        const int nfl = w * 2 + r;
        const int j = nfl * 8 + g;
#pragma unroll
        for (int kf = 0; kf < 4; kf++) {
            const int d0 = kf * 16 + 2 * q;
            uint4 v;
            pack2hl(t[j][d0], t[j][d0 + 1], v.x, v.z);
            pack2hl(t[j][d0 + 8], t[j][d0 + 9], v.y, v.w);
            g_fx3[((size_t)(b * 256 + (s0 >> 3) + nfl) * 4 + kf) * 32 + lane] = v;
        }
    }
}

// ---- k0w: W_V -> A-frag layout (one block per row) -------------------------
__global__ __launch_bounds__(256) void k0_wv(const float* __restrict__ WV) {
    const int row = blockIdx.x, tid = threadIdx.x;
    const float* src = WV + (size_t)row * S + tid * 8;
    float wv[8];
#pragma unroll
    for (int j = 0; j < 8; j++) wv[j] = src[j];
    write_a_frags(wv, row, tid, (uint32_t*)g_fav_h, (uint32_t*)g_fav_l);
}

// ---- k1: W_Q'[i,u] = sum_{t>=u} W_Q[i,t]/(t+1) -> A-frag layout ------------
__global__ __launch_bounds__(256) void k1_suffix(const float* __restrict__ WQ) {
    const int row = blockIdx.x, tid = threadIdx.x, base = tid * 8;
    const float* src = WQ + (size_t)row * S;
    float v[8], local = 0.f;
#pragma unroll
    for (int k = 0; k < 8; k++) { v[k] = src[base + k] / (float)(base + k + 1); local += v[k]; }
    float pre = local;
    const int lane = tid & 31, warp = tid >> 5;
#pragma unroll
    for (int off = 1; off < 32; off <<= 1) {
        float n = __shfl_up_sync(0xffffffff, pre, off);
        if (lane >= off) pre += n;
    }
    __shared__ float wsum[8], wpre[8], stot;
    if (lane == 31) wsum[warp] = pre;
    __syncthreads();
    if (tid == 0) {
        float acc = 0.f;
#pragma unroll
        for (int w = 0; w < 8; w++) { wpre[w] = acc; acc += wsum[w]; }
        stot = acc;
    }
    __syncthreads();
    float run = wpre[warp] + (pre - local);
    float wv[8];
#pragma unroll
    for (int k = 0; k < 8; k++) { wv[k] = stot - run; run += v[k]; }
    write_a_frags(wv, row, tid, (uint32_t*)g_faq_h, (uint32_t*)g_faq_l);
}

// ---- k2: HMMA GEMM on fragment-linear operands (verified round 12) ---------
__global__ __launch_bounds__(256) void k2_hmma() {
    const int mt = blockIdx.x;
    const int mat = blockIdx.y >> 1, nh = blockIdx.y & 1;
    const int kq = blockIdx.z;
    const int wid = threadIdx.x >> 5, lane = threadIdx.x & 31;
    const int wm = wid & 3, wn = wid >> 2;
    const int mf = mt * 4 + wm;
    const int nfb = nh * 16 + wn * 8;

    const uint4* Ah = (mat ? g_fav_h : g_faq_h) + ((size_t)mf * KF + kq * 32) * 32 + lane;
    const uint4* Al = (mat ? g_fav_l : g_faq_l) + ((size_t)mf * KF + kq * 32) * 32 + lane;
    const uint4* Bp[8];
#pragma unroll
    for (int nt = 0; nt < 8; nt++)
        Bp[nt] = g_fbx + ((size_t)(nfb + nt) * KF + kq * 32) * 32 + lane;

    float acc[8][4];
#pragma unroll
    for (int t = 0; t < 8; t++)
#pragma unroll
        for (int c = 0; c < 4; c++) acc[t][c] = 0.f;

#pragma unroll 4
    for (int ks = 0; ks < 32; ks++) {
        const uint4 av = Ah[ks * 32];
        const uint4 lv = Al[ks * 32];
        const uint32_t ah[4] = {av.x, av.y, av.z, av.w};
        const uint32_t al[4] = {lv.x, lv.y, lv.z, lv.w};
#pragma unroll
        for (int nt = 0; nt < 8; nt++) {
            const uint4 bb = Bp[nt][ks * 32];
            hmma(acc[nt], ah, bb.x, bb.y);
            hmma(acc[nt], ah, bb.z, bb.w);
            hmma(acc[nt], al, bb.x, bb.y);
        }
    }
    const int g = lane >> 2;
    const int m0 = mf * 16;
    float* base = g_k2part + (size_t)(kq * 2 + mat) * B * S * D;
#pragma unroll
    for (int nt = 0; nt < 8; nt++) {
        const int n0 = (nfb + nt) * 8 + (lane & 3) * 2;
        const int b = n0 >> 6, d = n0 & 63;
        float* p0 = base + (((size_t)b * S + m0 + g) * D + d);
        float* p8 = base + (((size_t)b * S + m0 + g + 8) * D + d);
        *(float2*)p0 = make_float2(acc[nt][0], acc[nt][1]);
        *(float2*)p8 = make_float2(acc[nt][2], acc[nt][3]);
    }
}

// ---- k2r: sum 4 K-quarter partials -> g_Q / g_V ----------------------------
__global__ __launch_bounds__(256) void k2_reduce() {
    const size_t f = (size_t)blockIdx.x * 256 + threadIdx.x;
    const float4* p = (const float4*)g_k2part;
    const size_t stride = (size_t)2 * B * S * D / 4;
    float4 a = p[f];
#pragma unroll
    for (int kq = 1; kq < 4; kq++) {
        float4 q = p[kq * stride + f];
        a.x += q.x; a.y += q.y; a.z += q.z; a.w += q.w;
    }
    const size_t half = (size_t)B * S * D / 4;
    if (f < half) ((float4*)g_Q)[f] = a;
    else ((float4*)g_V)[f - half] = a;
}

// ---- k3qf: g_Q fp32 -> A-frag layout (k = d). one warp per mf --------------
__global__ __launch_bounds__(256) void k3_qfrag() {
    const int b = blockIdx.y;
    const int w = threadIdx.x >> 5, lane = threadIdx.x & 31;
    const int mf = blockIdx.x * 8 + w;
    const int g = lane >> 2, q = lane & 3;
    const float* Qb = g_Q + ((size_t)b * S + mf * 16) * D;
#pragma unroll
    for (int kf = 0; kf < 4; kf++) {
        const int d0 = kf * 16 + 2 * q;
        uint4 h, l;
        pack2hl(Qb[g * D + d0], Qb[g * D + d0 + 1], h.x, l.x);
        pack2hl(Qb[(g + 8) * D + d0], Qb[(g + 8) * D + d0 + 1], h.y, l.y);
        pack2hl(Qb[g * D + d0 + 8], Qb[g * D + d0 + 9], h.z, l.z);
        pack2hl(Qb[(g + 8) * D + d0 + 8], Qb[(g + 8) * D + d0 + 9], h.w, l.w);
        const size_t idx = ((size_t)(b * 128 + mf) * 4 + kf) * 32 + lane;
        g_fq3h[idx] = h;
        g_fq3l[idx] = l;
    }
}

// ---- k3: HMMA masked scores + fused per-column (m,z) partials ---------------
// 128(i) x 64(j) tiles; grid (16, 32, B). Partials per column: 16 (i-chunks).
__global__ __launch_bounds__(256) void k3_hmma() {
    const int ic = blockIdx.x, jc = blockIdx.y, b = blockIdx.z;
    const int i0 = ic * 128, j0 = jc * 64;
    const int tid = threadIdx.x;
    if (i0 + 127 < j0) {  // strictly upper: sentinel stats, no scores
        if (tid < 64) {
            const size_t o = ((size_t)b * 16 + ic) * S + j0 + tid;
            g_partM[o] = -1e38f;
            g_partZ[o] = 0.f;
        }
        return;
    }
    __shared__ float St[128][68];
    __shared__ float red_m[16][64], red_z[16][64];
    const int wid = tid >> 5, lane = tid & 31;
    const int wm = wid & 3, wn = wid >> 2;
    const int g = lane >> 2, q = lane & 3;

    float acc[2][4][4];
#pragma unroll
    for (int mp = 0; mp < 2; mp++)
#pragma unroll
        for (int nt = 0; nt < 4; nt++)
#pragma unroll
            for (int c = 0; c < 4; c++) acc[mp][nt][c] = 0.f;

    const uint4* Ah = g_fq3h + ((size_t)(b * 128 + ic * 8 + wm * 2) * 4) * 32 + lane;
    const uint4* Al = g_fq3l + ((size_t)(b * 128 + ic * 8 + wm * 2) * 4) * 32 + lane;
    const uint4* Bf = g_fx3 + ((size_t)(b * 256 + jc * 8 + wn * 4) * 4) * 32 + lane;

#pragma unroll
    for (int kf = 0; kf < 4; kf++) {
        const uint4 a0 = Ah[kf * 32], a1 = Ah[(4 + kf) * 32];
        const uint4 l0 = Al[kf * 32], l1 = Al[(4 + kf) * 32];
        const uint32_t ah0[4] = {a0.x, a0.y, a0.z, a0.w};
        const uint32_t ah1[4] = {a1.x, a1.y, a1.z, a1.w};
        const uint32_t al0[4] = {l0.x, l0.y, l0.z, l0.w};
        const uint32_t al1[4] = {l1.x, l1.y, l1.z, l1.w};
#pragma unroll
        for (int nt = 0; nt < 4; nt++) {
            const uint4 bb = Bf[(nt * 4 + kf) * 32];
            hmma(acc[0][nt], ah0, bb.x, bb.y);
            hmma(acc[0][nt], ah0, bb.z, bb.w);
            hmma(acc[0][nt], al0, bb.x, bb.y);
            hmma(acc[1][nt], ah1, bb.x, bb.y);
            hmma(acc[1][nt], ah1, bb.z, bb.w);
            hmma(acc[1][nt], al1, bb.x, bb.y);
        }
    }
    // frags -> smem tile
#pragma unroll
    for (int mp = 0; mp < 2; mp++)
#pragma unroll
        for (int nt = 0; nt < 4; nt++) {
            const int r0 = wm * 32 + mp * 16 + g, c0 = wn * 32 + nt * 8 + 2 * q;
            *(float2*)&St[r0][c0] = make_float2(acc[mp][nt][0], acc[mp][nt][1]);
            *(float2*)&St[r0 + 8][c0] = make_float2(acc[mp][nt][2], acc[mp][nt][3]);
        }
    __syncthreads();
    // round-8 epilogue on St: mask -> global scores -> column (m,z) partials
    const int tx = tid & 15, ty = tid >> 4;
    float* Sc = g_scores + (size_t)b * S * S;
    float mc[4] = {-1e38f, -1e38f, -1e38f, -1e38f};
    float ov[8][4];
#pragma unroll
    for (int r = 0; r < 8; r++) {
        const int gi = i0 + ty * 8 + r;
        const float4 v = *(const float4*)&St[ty * 8 + r][tx * 4];
        const float vv[4] = {v.x, v.y, v.z, v.w};
#pragma unroll
        for (int c = 0; c < 4; c++) {
            const int gj = j0 + tx * 4 + c;
            const float o = (gi >= gj && vv[c] > 1.0f) ? vv[c] : NEGBIG;
            ov[r][c] = o;
            mc[c] = fmaxf(mc[c], o * SCALE);
        }
    }
    float zc[4] = {0.f, 0.f, 0.f, 0.f};
#pragma unroll
    for (int r = 0; r < 8; r++) {
        const int gi = i0 + ty * 8 + r;
        *(float4*)&Sc[(size_t)gi * S + j0 + tx * 4] =
            make_float4(ov[r][0], ov[r][1], ov[r][2], ov[r][3]);
#pragma unroll
        for (int c = 0; c < 4; c++) zc[c] += __expf(ov[r][c] * SCALE - mc[c]);
    }
#pragma unroll
    for (int c = 0; c < 4; c++) {
        red_m[ty][tx * 4 + c] = mc[c];
        red_z[ty][tx * 4 + c] = zc[c];
    }
    __syncthreads();
    if (tid < 64) {
        float m = -1e38f;
#pragma unroll
        for (int t = 0; t < 16; t++) m = fmaxf(m, red_m[t][tid]);
        float z = 0.f;
#pragma unroll
        for (int t = 0; t < 16; t++) z += red_z[t][tid] * __expf(red_m[t][tid] - m);
        const size_t o = ((size_t)b * 16 + ic) * S + j0 + tid;
        g_partM[o] = m;
        g_partZ[o] = z;
    }
}

// ---- k4b: reduce 16 partials -> colC[j] = m_j + log(z_j) -------------------
__global__ __launch_bounds__(256) void k4b_reduce() {
    const int j = blockIdx.x * 256 + threadIdx.x, b = blockIdx.y;
    float pm[16], pz[16];
#pragma unroll
    for (int i = 0; i < 16; i++) {
        pm[i] = g_partM[((size_t)b * 16 + i) * S + j];
        pz[i] = g_partZ[((size_t)b * 16 + i) * S + j];
    }
    float m = -1e38f;
#pragma unroll
    for (int i = 0; i < 16; i++) m = fmaxf(m, pm[i]);
    float z = 0.f;
#pragma unroll
    for (int i = 0; i < 16; i++) z += pz[i] * __expf(pm[i] - m);
    g_colC[b * S + j] = m + logf(z);
}

// ---- k5: partial out = exp(s*scale - colC_j) @ V, split-K over j-tiles -----
__global__ __launch_bounds__(256) void k5_pv() {
    const int mb = blockIdx.x, sp = blockIdx.y, b = blockIdx.z;
    const int i0 = mb * 128;
    const float* Sc = g_scores + (size_t)b * S * S;
    const float* Vb = g_V + (size_t)b * S * D;
    const float* cC = g_colC + b * S;
    float* P = g_part + (size_t)(sp * B + b) * S * D;
    __shared__ float As[16][132];
    __shared__ float Bs[16][64];
    const int tid = threadIdx.x, tx = tid & 7, ty = tid >> 3;
    const int arow = tid >> 1, akq = (tid & 1) * 8;
    const int bk = tid >> 4, bd = (tid & 15) * 4;
    float acc[4][8];
#pragma unroll
    for (int i = 0; i < 4; i++)
#pragma unroll
        for (int j = 0; j < 8; j++) acc[i][j] = 0.f;
    for (int t = sp; t <= mb; t += KS) {
#pragma unroll 1
        for (int kk = 0; kk < 8; kk++) {
            const int k0 = t * 128 + kk * 16;
            const float* ap = &Sc[(size_t)(i0 + arow) * S + k0 + akq];
            float4 a0 = *(const float4*)ap, a1 = *(const float4*)(ap + 4);
            float4 c0 = *(const float4*)&cC[k0 + akq];
            float4 c1 = *(const float4*)&cC[k0 + akq + 4];
            float4 vb = *(const float4*)&Vb[(size_t)(k0 + bk) * D + bd];
            __syncthreads();
            As[akq + 0][arow] = __expf(fmaf(a0.x, SCALE, -c0.x));
            As[akq + 1][arow] = __expf(fmaf(a0.y, SCALE, -c0.y));
            As[akq + 2][arow] = __expf(fmaf(a0.z, SCALE, -c0.z));
            As[akq + 3][arow] = __expf(fmaf(a0.w, SCALE, -c0.w));
            As[akq + 4][arow] = __expf(fmaf(a1.x, SCALE, -c1.x));
            As[akq + 5][arow] = __expf(fmaf(a1.y, SCALE, -c1.y));
            As[akq + 6][arow] = __expf(fmaf(a1.z, SCALE, -c1.z));
            As[akq + 7][arow] = __expf(fmaf(a1.w, SCALE, -c1.w));
            *(float4*)&Bs[bk][bd] = vb;
            __syncthreads();
#pragma unroll
            for (int k = 0; k < 16; k++) {
                float4 a4 = *(const float4*)&As[k][ty * 4];
                float4 b0 = *(const float4*)&Bs[k][tx * 4];
                float4 b1 = *(const float4*)&Bs[k][32 + tx * 4];
                float av[4] = {a4.x, a4.y, a4.z, a4.w};
                float bv[8] = {b0.x, b0.y, b0.z, b0.w, b1.x, b1.y, b1.z, b1.w};
#pragma unroll
                for (int i = 0; i < 4; i++)
#pragma unroll
                    for (int j = 0; j < 8; j++) acc[i][j] = fmaf(av[i], bv[j], acc[i][j]);
            }
        }
    }
#pragma unroll
    for (int i = 0; i < 4; i++) {
        float* o = &P[(size_t)(i0 + ty * 4 + i) * D];
        *(float4*)&o[tx * 4] = make_float4(acc[i][0], acc[i][1], acc[i][2], acc[i][3]);
        *(float4*)&o[32 + tx * 4] = make_float4(acc[i][4], acc[i][5], acc[i][6], acc[i][7]);
    }
}

// ---- k6: reduce KS split-K partials into d_out -----------------------------
__global__ __launch_bounds__(256) void k6_reduce(float* __restrict__ out) {
    const int idx = blockIdx.x * 256 + threadIdx.x;
    const float4* p = (const float4*)g_part;
    const size_t n4 = (size_t)B * S * D / 4;
    float4 a = p[idx];
#pragma unroll
    for (int sp = 1; sp < KS; sp++) {
        float4 q = p[sp * n4 + idx];
        a.x += q.x; a.y += q.y; a.z += q.z; a.w += q.w;
    }
    ((float4*)out)[idx] = a;
}

extern "C" void kernel_launch(void* const* d_in, const int* in_sizes, int n_in,
                              void* d_out, int out_size) {
    int xi = 0;
    for (int i = 0; i < n_in; i++)
        if (in_sizes[i] == B * S * D) { xi = i; break; }
    int o1 = -1, o2 = -1;
    for (int i = 0; i < n_in; i++)
        if (i != xi) { if (o1 < 0) o1 = i; else o2 = i; }
    const float* x = (const float*)d_in[xi];
    const float* WQ = (const float*)d_in[o1];
    const float* WV = (const float*)d_in[o2];

    k0_x<<<dim3(S / 128, B), 256>>>(x);
    k0_wv<<<S, 256>>>(WV);
    k1_suffix<<<S, 256>>>(WQ);
    k2_hmma<<<dim3(32, 4, 4), 256>>>();
    k2_reduce<<<(2 * B * S * D / 4) / 256, 256>>>();
    k3_qfrag<<<dim3(16, B), 256>>>();
    k3_hmma<<<dim3(16, 32, B), 256>>>();
    k4b_reduce<<<dim3(S / 256, B), 256>>>();
    k5_pv<<<dim3(16, KS, B), 256>>>();
    k6_reduce<<<(B * S * D / 4) / 256, 256>>>((float*)d_out);
}

// round 14
// speedup vs baseline: 2.1698x; 1.0863x over previous
#include <cuda_runtime.h>
#include <cuda_bf16.h>
#include <cstdint>

namespace {
constexpr int B = 4, S = 2048, D = 64, KS = 8;
constexpr int MF = S / 16, KF = S / 16, NF = (B * D) / 8;  // 128, 128, 32
constexpr float SCALE = 0.022097086912079612f;  // 1/sqrt(2048)
constexpr float NEGBIG = -3.402823466e38f;
}

// ---- fragment-linear scratch: frag[(mf*KF+kf)*32 + lane] = uint4 ----------
__device__ uint4 g_faq_h[(size_t)MF * KF * 32];  // W_Q' hi  (a0,a1,a2,a3)
__device__ uint4 g_faq_l[(size_t)MF * KF * 32];  // W_Q' lo
__device__ uint4 g_fav_h[(size_t)MF * KF * 32];  // W_V  hi
__device__ uint4 g_fav_l[(size_t)MF * KF * 32];  // W_V  lo
__device__ uint4 g_fbx[(size_t)NF * KF * 32];    // x (k=s): (bh0,bh1,bl0,bl1)
// k3 fragments: Q as A-frags (k=d), x as B-frags (n=j, k=d)
__device__ uint4 g_fq3h[(size_t)B * 128 * 4 * 32];
__device__ uint4 g_fq3l[(size_t)B * 128 * 4 * 32];
__device__ uint4 g_fx3[(size_t)B * 256 * 4 * 32];
__device__ float g_k2part[(size_t)4 * 2 * B * S * D];  // [kq][mat][b][s][d]
__device__ float g_Q[(size_t)B * S * D];
__device__ float g_V[(size_t)B * S * D];
__device__ float g_scores[(size_t)B * S * S];
__device__ float g_partM[B * 16 * S];
__device__ float g_partZ[B * 16 * S];
__device__ float g_colC[B * S];
__device__ float g_part[(size_t)KS * B * S * D];

// ---- helpers ---------------------------------------------------------------
__device__ __forceinline__ void hmma(float* c, const uint32_t* a, uint32_t b0, uint32_t b1) {
    asm volatile(
        "mma.sync.aligned.m16n8k16.row.col.f32.bf16.bf16.f32 "
        "{%0,%1,%2,%3}, {%4,%5,%6,%7}, {%8,%9}, {%0,%1,%2,%3};"
        : "+f"(c[0]), "+f"(c[1]), "+f"(c[2]), "+f"(c[3])
        : "r"(a[0]), "r"(a[1]), "r"(a[2]), "r"(a[3]), "r"(b0), "r"(b1));
}
__device__ __forceinline__ uint32_t bpack(__nv_bfloat16 e, __nv_bfloat16 o) {
    return (uint32_t)__bfloat16_as_ushort(e) | ((uint32_t)__bfloat16_as_ushort(o) << 16);
}
__device__ __forceinline__ void bsplit(float v, __nv_bfloat16& h, __nv_bfloat16& l) {
    h = __float2bfloat16(v);
    l = __float2bfloat16(v - __bfloat162float(h));
}
__device__ __forceinline__ void pack2hl(float a, float b, uint32_t& hi, uint32_t& lo) {
    __nv_bfloat16 ha, la, hb, lb;
    bsplit(a, ha, la); bsplit(b, hb, lb);
    hi = bpack(ha, hb); lo = bpack(la, lb);
}

// writes one row's 8 consecutive-k fp32 values into A-frag layout (hi+lo)
__device__ __forceinline__ void write_a_frags(const float* wv, int row, int tid,
                                              uint32_t* outh, uint32_t* outl) {
    const int mf = row >> 4, g = row & 7;
    const int reg = (((row & 15) < 8) ? 0 : 1) + ((tid & 1) ? 2 : 0);
    const int kf = tid >> 1;
    __nv_bfloat16 h[8], l[8];
#pragma unroll
    for (int j = 0; j < 8; j++) bsplit(wv[j], h[j], l[j]);
#pragma unroll
    for (int q = 0; q < 4; q++) {
        const size_t idx = (((size_t)mf * KF + kf) * 32 + g * 4 + q) * 4 + reg;
        outh[idx] = bpack(h[2 * q], h[2 * q + 1]);
        outl[idx] = bpack(l[2 * q], l[2 * q + 1]);
    }
}

// ---- k0x: x -> k2 B-frags (k=s) AND k3 B-frags (n=j, k=d) ------------------
__global__ __launch_bounds__(256) void k0_x(const float* __restrict__ x) {
    __shared__ float t[128][65];
    const int s0 = blockIdx.x * 128, b = blockIdx.y;
    const float* xb = x + (size_t)b * S * D;
    for (int i = threadIdx.x; i < 128 * 64; i += 256)
        t[i >> 6][i & 63] = xb[(size_t)(s0 + (i >> 6)) * D + (i & 63)];
    __syncthreads();
    const int w = threadIdx.x >> 5, lane = threadIdx.x & 31;
    const int g = lane >> 2, q = lane & 3;
    {   // k2 B-frags: n = b*64+d, k = s
        const int nf = b * 8 + w, d = w * 8 + g;
#pragma unroll
        for (int kfl = 0; kfl < 8; kfl++) {
            const int sb = kfl * 16;
            uint4 v;
            pack2hl(t[sb + 2 * q][d], t[sb + 2 * q + 1][d], v.x, v.z);
            pack2hl(t[sb + 8 + 2 * q][d], t[sb + 9 + 2 * q][d], v.y, v.w);
            g_fbx[((size_t)nf * KF + (s0 >> 4) + kfl) * 32 + lane] = v;
        }
    }
    // k3 B-frags: n = j (seq), k = d. warp handles 2 nf.
#pragma unroll
    for (int r = 0; r < 2; r++) {
        const int nfl = w * 2 + r;
        const int j = nfl * 8 + g;
#pragma unroll
        for (int kf = 0; kf < 4; kf++) {
            const int d0 = kf * 16 + 2 * q;
            uint4 v;
            pack2hl(t[j][d0], t[j][d0 + 1], v.x, v.z);
            pack2hl(t[j][d0 + 8], t[j][d0 + 9], v.y, v.w);
            g_fx3[((size_t)(b * 256 + (s0 >> 3) + nfl) * 4 + kf) * 32 + lane] = v;
        }
    }
}

// ---- k0w: W_V -> A-frag layout (one block per row) -------------------------
__global__ __launch_bounds__(256) void k0_wv(const float* __restrict__ WV) {
    const int row = blockIdx.x, tid = threadIdx.x;
    const float* src = WV + (size_t)row * S + tid * 8;
    float wv[8];
#pragma unroll
    for (int j = 0; j < 8; j++) wv[j] = src[j];
    write_a_frags(wv, row, tid, (uint32_t*)g_fav_h, (uint32_t*)g_fav_l);
}

// ---- k1: W_Q'[i,u] = sum_{t>=u} W_Q[i,t]/(t+1) -> A-frag layout ------------
__global__ __launch_bounds__(256) void k1_suffix(const float* __restrict__ WQ) {
    const int row = blockIdx.x, tid = threadIdx.x, base = tid * 8;
    const float* src = WQ + (size_t)row * S;
    float v[8], local = 0.f;
#pragma unroll
    for (int k = 0; k < 8; k++) { v[k] = src[base + k] / (float)(base + k + 1); local += v[k]; }
    float pre = local;
    const int lane = tid & 31, warp = tid >> 5;
#pragma unroll
    for (int off = 1; off < 32; off <<= 1) {
        float n = __shfl_up_sync(0xffffffff, pre, off);
        if (lane >= off) pre += n;
    }
    __shared__ float wsum[8], wpre[8], stot;
    if (lane == 31) wsum[warp] = pre;
    __syncthreads();
    if (tid == 0) {
        float acc = 0.f;
#pragma unroll
        for (int w = 0; w < 8; w++) { wpre[w] = acc; acc += wsum[w]; }
        stot = acc;
    }
    __syncthreads();
    float run = wpre[warp] + (pre - local);
    float wv[8];
#pragma unroll
    for (int k = 0; k < 8; k++) { wv[k] = stot - run; run += v[k]; }
    write_a_frags(wv, row, tid, (uint32_t*)g_faq_h, (uint32_t*)g_faq_l);
}

// ---- k2: HMMA GEMM, nt=4 per warp for 2 blocks/SM --------------------------
// grid (32 m-tiles, mat*4+nq, 4 kq). 8 warps = 4m x 2n; block covers 8 nf.
__global__ __launch_bounds__(256, 2) void k2_hmma() {
    const int mt = blockIdx.x;
    const int mat = blockIdx.y >> 2, nq = blockIdx.y & 3;
    const int kq = blockIdx.z;
    const int wid = threadIdx.x >> 5, lane = threadIdx.x & 31;
    const int wm = wid & 3, wn = wid >> 2;
    const int mf = mt * 4 + wm;
    const int nfb = nq * 8 + wn * 4;

    const uint4* Ah = (mat ? g_fav_h : g_faq_h) + ((size_t)mf * KF + kq * 32) * 32 + lane;
    const uint4* Al = (mat ? g_fav_l : g_faq_l) + ((size_t)mf * KF + kq * 32) * 32 + lane;
    const uint4* Bp[4];
#pragma unroll
    for (int nt = 0; nt < 4; nt++)
        Bp[nt] = g_fbx + ((size_t)(nfb + nt) * KF + kq * 32) * 32 + lane;

    float acc[4][4];
#pragma unroll
    for (int t = 0; t < 4; t++)
#pragma unroll
        for (int c = 0; c < 4; c++) acc[t][c] = 0.f;

#pragma unroll 4
    for (int ks = 0; ks < 32; ks++) {
        const uint4 av = Ah[ks * 32];
        const uint4 lv = Al[ks * 32];
        const uint32_t ah[4] = {av.x, av.y, av.z, av.w};
        const uint32_t al[4] = {lv.x, lv.y, lv.z, lv.w};
#pragma unroll
        for (int nt = 0; nt < 4; nt++) {
            const uint4 bb = Bp[nt][ks * 32];
            hmma(acc[nt], ah, bb.x, bb.y);  // hi*hi
            hmma(acc[nt], ah, bb.z, bb.w);  // hi*lo
            hmma(acc[nt], al, bb.x, bb.y);  // lo*hi
        }
    }
    const int g = lane >> 2;
    const int m0 = mf * 16;
    float* base = g_k2part + (size_t)(kq * 2 + mat) * B * S * D;
#pragma unroll
    for (int nt = 0; nt < 4; nt++) {
        const int n0 = (nfb + nt) * 8 + (lane & 3) * 2;
        const int b = n0 >> 6, d = n0 & 63;
        float* p0 = base + (((size_t)b * S + m0 + g) * D + d);
        float* p8 = base + (((size_t)b * S + m0 + g + 8) * D + d);
        *(float2*)p0 = make_float2(acc[nt][0], acc[nt][1]);
        *(float2*)p8 = make_float2(acc[nt][2], acc[nt][3]);
    }
}

// ---- k2r: sum 4 K-quarter partials -> g_Q / g_V ----------------------------
__global__ __launch_bounds__(256) void k2_reduce() {
    const size_t f = (size_t)blockIdx.x * 256 + threadIdx.x;
    const float4* p = (const float4*)g_k2part;
    const size_t stride = (size_t)2 * B * S * D / 4;
    float4 a = p[f];
#pragma unroll
    for (int kq = 1; kq < 4; kq++) {
        float4 q = p[kq * stride + f];
        a.x += q.x; a.y += q.y; a.z += q.z; a.w += q.w;
    }
    const size_t half = (size_t)B * S * D / 4;
    if (f < half) ((float4*)g_Q)[f] = a;
    else ((float4*)g_V)[f - half] = a;
}

// ---- k3qf: g_Q fp32 -> A-frag layout (k = d). one warp per mf --------------
__global__ __launch_bounds__(256) void k3_qfrag() {
    const int b = blockIdx.y;
    const int w = threadIdx.x >> 5, lane = threadIdx.x & 31;
    const int mf = blockIdx.x * 8 + w;
    const int g = lane >> 2, q = lane & 3;
    const float* Qb = g_Q + ((size_t)b * S + mf * 16) * D;
#pragma unroll
    for (int kf = 0; kf < 4; kf++) {
        const int d0 = kf * 16 + 2 * q;
        uint4 h, l;
        pack2hl(Qb[g * D + d0], Qb[g * D + d0 + 1], h.x, l.x);
        pack2hl(Qb[(g + 8) * D + d0], Qb[(g + 8) * D + d0 + 1], h.y, l.y);
        pack2hl(Qb[g * D + d0 + 8], Qb[g * D + d0 + 9], h.z, l.z);
        pack2hl(Qb[(g + 8) * D + d0 + 8], Qb[(g + 8) * D + d0 + 9], h.w, l.w);
        const size_t idx = ((size_t)(b * 128 + mf) * 4 + kf) * 32 + lane;
        g_fq3h[idx] = h;
        g_fq3l[idx] = l;
    }
}

// ---- k3: HMMA masked scores + fused per-column (m,z) partials ---------------
__global__ __launch_bounds__(256) void k3_hmma() {
    const int ic = blockIdx.x, jc = blockIdx.y, b = blockIdx.z;
    const int i0 = ic * 128, j0 = jc * 64;
    const int tid = threadIdx.x;
    if (i0 + 127 < j0) {
        if (tid < 64) {
            const size_t o = ((size_t)b * 16 + ic) * S + j0 + tid;
            g_partM[o] = -1e38f;
            g_partZ[o] = 0.f;
        }
        return;
    }
    __shared__ float St[128][68];
    __shared__ float red_m[16][64], red_z[16][64];
    const int wid = tid >> 5, lane = tid & 31;
    const int wm = wid & 3, wn = wid >> 2;
    const int g = lane >> 2, q = lane & 3;

    float acc[2][4][4];
#pragma unroll
    for (int mp = 0; mp < 2; mp++)
#pragma unroll
        for (int nt = 0; nt < 4; nt++)
#pragma unroll
            for (int c = 0; c < 4; c++) acc[mp][nt][c] = 0.f;

    const uint4* Ah = g_fq3h + ((size_t)(b * 128 + ic * 8 + wm * 2) * 4) * 32 + lane;
    const uint4* Al = g_fq3l + ((size_t)(b * 128 + ic * 8 + wm * 2) * 4) * 32 + lane;
    const uint4* Bf = g_fx3 + ((size_t)(b * 256 + jc * 8 + wn * 4) * 4) * 32 + lane;

#pragma unroll
    for (int kf = 0; kf < 4; kf++) {
        const uint4 a0 = Ah[kf * 32], a1 = Ah[(4 + kf) * 32];
        const uint4 l0 = Al[kf * 32], l1 = Al[(4 + kf) * 32];
        const uint32_t ah0[4] = {a0.x, a0.y, a0.z, a0.w};
        const uint32_t ah1[4] = {a1.x, a1.y, a1.z, a1.w};
        const uint32_t al0[4] = {l0.x, l0.y, l0.z, l0.w};
        const uint32_t al1[4] = {l1.x, l1.y, l1.z, l1.w};
#pragma unroll
        for (int nt = 0; nt < 4; nt++) {
            const uint4 bb = Bf[(nt * 4 + kf) * 32];
            hmma(acc[0][nt], ah0, bb.x, bb.y);
            hmma(acc[0][nt], ah0, bb.z, bb.w);
            hmma(acc[0][nt], al0, bb.x, bb.y);
            hmma(acc[1][nt], ah1, bb.x, bb.y);
            hmma(acc[1][nt], ah1, bb.z, bb.w);
            hmma(acc[1][nt], al1, bb.x, bb.y);
        }
    }
#pragma unroll
    for (int mp = 0; mp < 2; mp++)
#pragma unroll
        for (int nt = 0; nt < 4; nt++) {
            const int r0 = wm * 32 + mp * 16 + g, c0 = wn * 32 + nt * 8 + 2 * q;
            *(float2*)&St[r0][c0] = make_float2(acc[mp][nt][0], acc[mp][nt][1]);
            *(float2*)&St[r0 + 8][c0] = make_float2(acc[mp][nt][2], acc[mp][nt][3]);
        }
    __syncthreads();
    const int tx = tid & 15, ty = tid >> 4;
    float* Sc = g_scores + (size_t)b * S * S;
    float mc[4] = {-1e38f, -1e38f, -1e38f, -1e38f};
    float ov[8][4];
#pragma unroll
    for (int r = 0; r < 8; r++) {
        const int gi = i0 + ty * 8 + r;
        const float4 v = *(const float4*)&St[ty * 8 + r][tx * 4];
        const float vv[4] = {v.x, v.y, v.z, v.w};
#pragma unroll
        for (int c = 0; c < 4; c++) {
            const int gj = j0 + tx * 4 + c;
            const float o = (gi >= gj && vv[c] > 1.0f) ? vv[c] : NEGBIG;
            ov[r][c] = o;
            mc[c] = fmaxf(mc[c], o * SCALE);
        }
    }
    float zc[4] = {0.f, 0.f, 0.f, 0.f};
#pragma unroll
    for (int r = 0; r < 8; r++) {
        const int gi = i0 + ty * 8 + r;
        *(float4*)&Sc[(size_t)gi * S + j0 + tx * 4] =
            make_float4(ov[r][0], ov[r][1], ov[r][2], ov[r][3]);
#pragma unroll
        for (int c = 0; c < 4; c++) zc[c] += __expf(ov[r][c] * SCALE - mc[c]);
    }
#pragma unroll
    for (int c = 0; c < 4; c++) {
        red_m[ty][tx * 4 + c] = mc[c];
        red_z[ty][tx * 4 + c] = zc[c];
    }
    __syncthreads();
    if (tid < 64) {
        float m = -1e38f;
#pragma unroll
        for (int t = 0; t < 16; t++) m = fmaxf(m, red_m[t][tid]);
        float z = 0.f;
#pragma unroll
        for (int t = 0; t < 16; t++) z += red_z[t][tid] * __expf(red_m[t][tid] - m);
        const size_t o = ((size_t)b * 16 + ic) * S + j0 + tid;
        g_partM[o] = m;
        g_partZ[o] = z;
    }
}

// ---- k4b: reduce 16 partials -> colC[j] = m_j + log(z_j) -------------------
__global__ __launch_bounds__(256) void k4b_reduce() {
    const int j = blockIdx.x * 256 + threadIdx.x, b = blockIdx.y;
    float pm[16], pz[16];
#pragma unroll
    for (int i = 0; i < 16; i++) {
        pm[i] = g_partM[((size_t)b * 16 + i) * S + j];
        pz[i] = g_partZ[((size_t)b * 16 + i) * S + j];
    }
    float m = -1e38f;
#pragma unroll
    for (int i = 0; i < 16; i++) m = fmaxf(m, pm[i]);
    float z = 0.f;
#pragma unroll
    for (int i = 0; i < 16; i++) z += pz[i] * __expf(pm[i] - m);
    g_colC[b * S + j] = m + logf(z);
}

// ---- k5: partial out = exp(s*scale - colC_j) @ V, split-K over j-tiles -----
__global__ __launch_bounds__(256) void k5_pv() {
    const int mb = blockIdx.x, sp = blockIdx.y, b = blockIdx.z;
    const int i0 = mb * 128;
    const float* Sc = g_scores + (size_t)b * S * S;
    const float* Vb = g_V + (size_t)b * S * D;
    const float* cC = g_colC + b * S;
    float* P = g_part + (size_t)(sp * B + b) * S * D;
    __shared__ float As[16][132];
    __shared__ float Bs[16][64];
    const int tid = threadIdx.x, tx = tid & 7, ty = tid >> 3;
    const int arow = tid >> 1, akq = (tid & 1) * 8;
    const int bk = tid >> 4, bd = (tid & 15) * 4;
    float acc[4][8];
#pragma unroll
    for (int i = 0; i < 4; i++)
#pragma unroll
        for (int j = 0; j < 8; j++) acc[i][j] = 0.f;
    for (int t = sp; t <= mb; t += KS) {
#pragma unroll 1
        for (int kk = 0; kk < 8; kk++) {
            const int k0 = t * 128 + kk * 16;
            const float* ap = &Sc[(size_t)(i0 + arow) * S + k0 + akq];
            float4 a0 = *(const float4*)ap, a1 = *(const float4*)(ap + 4);
            float4 c0 = *(const float4*)&cC[k0 + akq];
            float4 c1 = *(const float4*)&cC[k0 + akq + 4];
            float4 vb = *(const float4*)&Vb[(size_t)(k0 + bk) * D + bd];
            __syncthreads();
            As[akq + 0][arow] = __expf(fmaf(a0.x, SCALE, -c0.x));
            As[akq + 1][arow] = __expf(fmaf(a0.y, SCALE, -c0.y));
            As[akq + 2][arow] = __expf(fmaf(a0.z, SCALE, -c0.z));
            As[akq + 3][arow] = __expf(fmaf(a0.w, SCALE, -c0.w));
            As[akq + 4][arow] = __expf(fmaf(a1.x, SCALE, -c1.x));
            As[akq + 5][arow] = __expf(fmaf(a1.y, SCALE, -c1.y));
            As[akq + 6][arow] = __expf(fmaf(a1.z, SCALE, -c1.z));
            As[akq + 7][arow] = __expf(fmaf(a1.w, SCALE, -c1.w));
            *(float4*)&Bs[bk][bd] = vb;
            __syncthreads();
#pragma unroll
            for (int k = 0; k < 16; k++) {
                float4 a4 = *(const float4*)&As[k][ty * 4];
                float4 b0 = *(const float4*)&Bs[k][tx * 4];
                float4 b1 = *(const float4*)&Bs[k][32 + tx * 4];
                float av[4] = {a4.x, a4.y, a4.z, a4.w};
                float bv[8] = {b0.x, b0.y, b0.z, b0.w, b1.x, b1.y, b1.z, b1.w};
#pragma unroll
                for (int i = 0; i < 4; i++)
#pragma unroll
                    for (int j = 0; j < 8; j++) acc[i][j] = fmaf(av[i], bv[j], acc[i][j]);
            }
        }
    }
#pragma unroll
    for (int i = 0; i < 4; i++) {
        float* o = &P[(size_t)(i0 + ty * 4 + i) * D];
        *(float4*)&o[tx * 4] = make_float4(acc[i][0], acc[i][1], acc[i][2], acc[i][3]);
        *(float4*)&o[32 + tx * 4] = make_float4(acc[i][4], acc[i][5], acc[i][6], acc[i][7]);
    }
}

// ---- k6: reduce KS split-K partials into d_out -----------------------------
__global__ __launch_bounds__(256) void k6_reduce(float* __restrict__ out) {
    const int idx = blockIdx.x * 256 + threadIdx.x;
    const float4* p = (const float4*)g_part;
    const size_t n4 = (size_t)B * S * D / 4;
    float4 a = p[idx];
#pragma unroll
    for (int sp = 1; sp < KS; sp++) {
        float4 q = p[sp * n4 + idx];
        a.x += q.x; a.y += q.y; a.z += q.z; a.w += q.w;
    }
    ((float4*)out)[idx] = a;
}

extern "C" void kernel_launch(void* const* d_in, const int* in_sizes, int n_in,
                              void* d_out, int out_size) {
    int xi = 0;
    for (int i = 0; i < n_in; i++)
        if (in_sizes[i] == B * S * D) { xi = i; break; }
    int o1 = -1, o2 = -1;
    for (int i = 0; i < n_in; i++)
        if (i != xi) { if (o1 < 0) o1 = i; else o2 = i; }
    const float* x = (const float*)d_in[xi];
    const float* WQ = (const float*)d_in[o1];
    const float* WV = (const float*)d_in[o2];

    k0_x<<<dim3(S / 128, B), 256>>>(x);
    k0_wv<<<S, 256>>>(WV);
    k1_suffix<<<S, 256>>>(WQ);
    k2_hmma<<<dim3(32, 8, 4), 256>>>();
    k2_reduce<<<(2 * B * S * D / 4) / 256, 256>>>();
    k3_qfrag<<<dim3(16, B), 256>>>();
    k3_hmma<<<dim3(16, 32, B), 256>>>();
    k4b_reduce<<<dim3(S / 256, B), 256>>>();
    k5_pv<<<dim3(16, KS, B), 256>>>();
    k6_reduce<<<(B * S * D / 4) / 256, 256>>>((float*)d_out);
}

// round 15
// speedup vs baseline: 2.1970x; 1.0125x over previous
#include <cuda_runtime.h>
#include <cuda_bf16.h>
#include <cstdint>

namespace {
constexpr int B = 4, S = 2048, D = 64, KS = 4;
constexpr int MF = S / 16, KF = S / 16, NF = (B * D) / 8;  // 128, 128, 32
constexpr float SCALE = 0.022097086912079612f;  // 1/sqrt(2048)
constexpr float NEGBIG = -3.402823466e38f;
}

// ---- fragment-linear scratch: frag[(mf*KF+kf)*32 + lane] = uint4 ----------
__device__ uint4 g_faq_h[(size_t)MF * KF * 32];  // W_Q' hi  (a0,a1,a2,a3)
__device__ uint4 g_faq_l[(size_t)MF * KF * 32];  // W_Q' lo
__device__ uint4 g_fav_h[(size_t)MF * KF * 32];  // W_V  hi
__device__ uint4 g_fav_l[(size_t)MF * KF * 32];  // W_V  lo
__device__ uint4 g_fbx[(size_t)NF * KF * 32];    // x (k=s): (bh0,bh1,bl0,bl1)
// k3 fragments: Q as A-frags (k=d), x as B-frags (n=j, k=d)
__device__ uint4 g_fq3h[(size_t)B * 128 * 4 * 32];
__device__ uint4 g_fq3l[(size_t)B * 128 * 4 * 32];
__device__ uint4 g_fx3[(size_t)B * 256 * 4 * 32];
// k5 fragments: V as B-frags (n=d, k=j), hi/lo packed
__device__ uint4 g_fv5[(size_t)B * 8 * 128 * 32];
__device__ float g_k2part[(size_t)4 * 2 * B * S * D];  // [kq][mat][b][s][d]
__device__ float g_Q[(size_t)B * S * D];
__device__ float g_V[(size_t)B * S * D];
__device__ float g_scores[(size_t)B * S * S];
__device__ float g_partM[B * 16 * S];
__device__ float g_partZ[B * 16 * S];
__device__ float g_colC[B * S];
__device__ float g_part[(size_t)KS * B * S * D];

// ---- helpers ---------------------------------------------------------------
__device__ __forceinline__ void hmma(float* c, const uint32_t* a, uint32_t b0, uint32_t b1) {
    asm volatile(
        "mma.sync.aligned.m16n8k16.row.col.f32.bf16.bf16.f32 "
        "{%0,%1,%2,%3}, {%4,%5,%6,%7}, {%8,%9}, {%0,%1,%2,%3};"
        : "+f"(c[0]), "+f"(c[1]), "+f"(c[2]), "+f"(c[3])
        : "r"(a[0]), "r"(a[1]), "r"(a[2]), "r"(a[3]), "r"(b0), "r"(b1));
}
__device__ __forceinline__ uint32_t bpack(__nv_bfloat16 e, __nv_bfloat16 o) {
    return (uint32_t)__bfloat16_as_ushort(e) | ((uint32_t)__bfloat16_as_ushort(o) << 16);
}
__device__ __forceinline__ void bsplit(float v, __nv_bfloat16& h, __nv_bfloat16& l) {
    h = __float2bfloat16(v);
    l = __float2bfloat16(v - __bfloat162float(h));
}
__device__ __forceinline__ void pack2hl(float a, float b, uint32_t& hi, uint32_t& lo) {
    __nv_bfloat16 ha, la, hb, lb;
    bsplit(a, ha, la); bsplit(b, hb, lb);
    hi = bpack(ha, hb); lo = bpack(la, lb);
}

// writes one row's 8 consecutive-k fp32 values into A-frag layout (hi+lo)
__device__ __forceinline__ void write_a_frags(const float* wv, int row, int tid,
                                              uint32_t* outh, uint32_t* outl) {
    const int mf = row >> 4, g = row & 7;
    const int reg = (((row & 15) < 8) ? 0 : 1) + ((tid & 1) ? 2 : 0);
    const int kf = tid >> 1;
    __nv_bfloat16 h[8], l[8];
#pragma unroll
    for (int j = 0; j < 8; j++) bsplit(wv[j], h[j], l[j]);
#pragma unroll
    for (int q = 0; q < 4; q++) {
        const size_t idx = (((size_t)mf * KF + kf) * 32 + g * 4 + q) * 4 + reg;
        outh[idx] = bpack(h[2 * q], h[2 * q + 1]);
        outl[idx] = bpack(l[2 * q], l[2 * q + 1]);
    }
}

// ---- k0x: x -> k2 B-frags (k=s) AND k3 B-frags (n=j, k=d) ------------------
__global__ __launch_bounds__(256) void k0_x(const float* __restrict__ x) {
    __shared__ float t[128][65];
    const int s0 = blockIdx.x * 128, b = blockIdx.y;
    const float* xb = x + (size_t)b * S * D;
    for (int i = threadIdx.x; i < 128 * 64; i += 256)
        t[i >> 6][i & 63] = xb[(size_t)(s0 + (i >> 6)) * D + (i & 63)];
    __syncthreads();
    const int w = threadIdx.x >> 5, lane = threadIdx.x & 31;
    const int g = lane >> 2, q = lane & 3;
    {   // k2 B-frags: n = b*64+d, k = s
        const int nf = b * 8 + w, d = w * 8 + g;
#pragma unroll
        for (int kfl = 0; kfl < 8; kfl++) {
            const int sb = kfl * 16;
            uint4 v;
            pack2hl(t[sb + 2 * q][d], t[sb + 2 * q + 1][d], v.x, v.z);
            pack2hl(t[sb + 8 + 2 * q][d], t[sb + 9 + 2 * q][d], v.y, v.w);
            g_fbx[((size_t)nf * KF + (s0 >> 4) + kfl) * 32 + lane] = v;
        }
    }
    // k3 B-frags: n = j (seq), k = d. warp handles 2 nf.
#pragma unroll
    for (int r = 0; r < 2; r++) {
        const int nfl = w * 2 + r;
        const int j = nfl * 8 + g;
#pragma unroll
        for (int kf = 0; kf < 4; kf++) {
            const int d0 = kf * 16 + 2 * q;
            uint4 v;
            pack2hl(t[j][d0], t[j][d0 + 1], v.x, v.z);
            pack2hl(t[j][d0 + 8], t[j][d0 + 9], v.y, v.w);
            g_fx3[((size_t)(b * 256 + (s0 >> 3) + nfl) * 4 + kf) * 32 + lane] = v;
        }
    }
}

// ---- k0w: W_V -> A-frag layout (one block per row) -------------------------
__global__ __launch_bounds__(256) void k0_wv(const float* __restrict__ WV) {
    const int row = blockIdx.x, tid = threadIdx.x;
    const float* src = WV + (size_t)row * S + tid * 8;
    float wv[8];
#pragma unroll
    for (int j = 0; j < 8; j++) wv[j] = src[j];
    write_a_frags(wv, row, tid, (uint32_t*)g_fav_h, (uint32_t*)g_fav_l);
}

// ---- k1: W_Q'[i,u] = sum_{t>=u} W_Q[i,t]/(t+1) -> A-frag layout ------------
__global__ __launch_bounds__(256) void k1_suffix(const float* __restrict__ WQ) {
    const int row = blockIdx.x, tid = threadIdx.x, base = tid * 8;
    const float* src = WQ + (size_t)row * S;
    float v[8], local = 0.f;
#pragma unroll
    for (int k = 0; k < 8; k++) { v[k] = src[base + k] / (float)(base + k + 1); local += v[k]; }
    float pre = local;
    const int lane = tid & 31, warp = tid >> 5;
#pragma unroll
    for (int off = 1; off < 32; off <<= 1) {
        float n = __shfl_up_sync(0xffffffff, pre, off);
        if (lane >= off) pre += n;
    }
    __shared__ float wsum[8], wpre[8], stot;
    if (lane == 31) wsum[warp] = pre;
    __syncthreads();
    if (tid == 0) {
        float acc = 0.f;
#pragma unroll
        for (int w = 0; w < 8; w++) { wpre[w] = acc; acc += wsum[w]; }
        stot = acc;
    }
    __syncthreads();
    float run = wpre[warp] + (pre - local);
    float wv[8];
#pragma unroll
    for (int k = 0; k < 8; k++) { wv[k] = stot - run; run += v[k]; }
    write_a_frags(wv, row, tid, (uint32_t*)g_faq_h, (uint32_t*)g_faq_l);
}

// ---- k2: HMMA GEMM, nt=4 per warp for 2 blocks/SM (verified round 14) ------
__global__ __launch_bounds__(256, 2) void k2_hmma() {
    const int mt = blockIdx.x;
    const int mat = blockIdx.y >> 2, nq = blockIdx.y & 3;
    const int kq = blockIdx.z;
    const int wid = threadIdx.x >> 5, lane = threadIdx.x & 31;
    const int wm = wid & 3, wn = wid >> 2;
    const int mf = mt * 4 + wm;
    const int nfb = nq * 8 + wn * 4;

    const uint4* Ah = (mat ? g_fav_h : g_faq_h) + ((size_t)mf * KF + kq * 32) * 32 + lane;
    const uint4* Al = (mat ? g_fav_l : g_faq_l) + ((size_t)mf * KF + kq * 32) * 32 + lane;
    const uint4* Bp[4];
#pragma unroll
    for (int nt = 0; nt < 4; nt++)
        Bp[nt] = g_fbx + ((size_t)(nfb + nt) * KF + kq * 32) * 32 + lane;

    float acc[4][4];
#pragma unroll
    for (int t = 0; t < 4; t++)
#pragma unroll
        for (int c = 0; c < 4; c++) acc[t][c] = 0.f;

#pragma unroll 4
    for (int ks = 0; ks < 32; ks++) {
        const uint4 av = Ah[ks * 32];
        const uint4 lv = Al[ks * 32];
        const uint32_t ah[4] = {av.x, av.y, av.z, av.w};
        const uint32_t al[4] = {lv.x, lv.y, lv.z, lv.w};
#pragma unroll
        for (int nt = 0; nt < 4; nt++) {
            const uint4 bb = Bp[nt][ks * 32];
            hmma(acc[nt], ah, bb.x, bb.y);
            hmma(acc[nt], ah, bb.z, bb.w);
            hmma(acc[nt], al, bb.x, bb.y);
        }
    }
    const int g = lane >> 2;
    const int m0 = mf * 16;
    float* base = g_k2part + (size_t)(kq * 2 + mat) * B * S * D;
#pragma unroll
    for (int nt = 0; nt < 4; nt++) {
        const int n0 = (nfb + nt) * 8 + (lane & 3) * 2;
        const int b = n0 >> 6, d = n0 & 63;
        float* p0 = base + (((size_t)b * S + m0 + g) * D + d);
        float* p8 = base + (((size_t)b * S + m0 + g + 8) * D + d);
        *(float2*)p0 = make_float2(acc[nt][0], acc[nt][1]);
        *(float2*)p8 = make_float2(acc[nt][2], acc[nt][3]);
    }
}

// ---- k2r: sum 4 K-quarter partials -> g_Q / g_V ----------------------------
__global__ __launch_bounds__(256) void k2_reduce() {
    const size_t f = (size_t)blockIdx.x * 256 + threadIdx.x;
    const float4* p = (const float4*)g_k2part;
    const size_t stride = (size_t)2 * B * S * D / 4;
    float4 a = p[f];
#pragma unroll
    for (int kq = 1; kq < 4; kq++) {
        float4 q = p[kq * stride + f];
        a.x += q.x; a.y += q.y; a.z += q.z; a.w += q.w;
    }
    const size_t half = (size_t)B * S * D / 4;
    if (f < half) ((float4*)g_Q)[f] = a;
    else ((float4*)g_V)[f - half] = a;
}

// ---- k3qf: g_Q fp32 -> A-frag layout (k = d). one warp per mf --------------
__global__ __launch_bounds__(256) void k3_qfrag() {
    const int b = blockIdx.y;
    const int w = threadIdx.x >> 5, lane = threadIdx.x & 31;
    const int mf = blockIdx.x * 8 + w;
    const int g = lane >> 2, q = lane & 3;
    const float* Qb = g_Q + ((size_t)b * S + mf * 16) * D;
#pragma unroll
    for (int kf = 0; kf < 4; kf++) {
        const int d0 = kf * 16 + 2 * q;
        uint4 h, l;
        pack2hl(Qb[g * D + d0], Qb[g * D + d0 + 1], h.x, l.x);
        pack2hl(Qb[(g + 8) * D + d0], Qb[(g + 8) * D + d0 + 1], h.y, l.y);
        pack2hl(Qb[g * D + d0 + 8], Qb[g * D + d0 + 9], h.z, l.z);
        pack2hl(Qb[(g + 8) * D + d0 + 8], Qb[(g + 8) * D + d0 + 9], h.w, l.w);
        const size_t idx = ((size_t)(b * 128 + mf) * 4 + kf) * 32 + lane;
        g_fq3h[idx] = h;
        g_fq3l[idx] = l;
    }
}

// ---- k3: HMMA masked scores + fused per-column (m,z) partials ---------------
__global__ __launch_bounds__(256) void k3_hmma() {
    const int ic = blockIdx.x, jc = blockIdx.y, b = blockIdx.z;
    const int i0 = ic * 128, j0 = jc * 64;
    const int tid = threadIdx.x;
    if (i0 + 127 < j0) {
        if (tid < 64) {
            const size_t o = ((size_t)b * 16 + ic) * S + j0 + tid;
            g_partM[o] = -1e38f;
            g_partZ[o] = 0.f;
        }
        return;
    }
    __shared__ float St[128][68];
    __shared__ float red_m[16][64], red_z[16][64];
    const int wid = tid >> 5, lane = tid & 31;
    const int wm = wid & 3, wn = wid >> 2;
    const int g = lane >> 2, q = lane & 3;

    float acc[2][4][4];
#pragma unroll
    for (int mp = 0; mp < 2; mp++)
#pragma unroll
        for (int nt = 0; nt < 4; nt++)
#pragma unroll
            for (int c = 0; c < 4; c++) acc[mp][nt][c] = 0.f;

    const uint4* Ah = g_fq3h + ((size_t)(b * 128 + ic * 8 + wm * 2) * 4) * 32 + lane;
    const uint4* Al = g_fq3l + ((size_t)(b * 128 + ic * 8 + wm * 2) * 4) * 32 + lane;
    const uint4* Bf = g_fx3 + ((size_t)(b * 256 + jc * 8 + wn * 4) * 4) * 32 + lane;

#pragma unroll
    for (int kf = 0; kf < 4; kf++) {
        const uint4 a0 = Ah[kf * 32], a1 = Ah[(4 + kf) * 32];
        const uint4 l0 = Al[kf * 32], l1 = Al[(4 + kf) * 32];
        const uint32_t ah0[4] = {a0.x, a0.y, a0.z, a0.w};
        const uint32_t ah1[4] = {a1.x, a1.y, a1.z, a1.w};
        const uint32_t al0[4] = {l0.x, l0.y, l0.z, l0.w};
        const uint32_t al1[4] = {l1.x, l1.y, l1.z, l1.w};
#pragma unroll
        for (int nt = 0; nt < 4; nt++) {
            const uint4 bb = Bf[(nt * 4 + kf) * 32];
            hmma(acc[0][nt], ah0, bb.x, bb.y);
            hmma(acc[0][nt], ah0, bb.z, bb.w);
            hmma(acc[0][nt], al0, bb.x, bb.y);
            hmma(acc[1][nt], ah1, bb.x, bb.y);
            hmma(acc[1][nt], ah1, bb.z, bb.w);
            hmma(acc[1][nt], al1, bb.x, bb.y);
        }
    }
#pragma unroll
    for (int mp = 0; mp < 2; mp++)
#pragma unroll
        for (int nt = 0; nt < 4; nt++) {
            const int r0 = wm * 32 + mp * 16 + g, c0 = wn * 32 + nt * 8 + 2 * q;
            *(float2*)&St[r0][c0] = make_float2(acc[mp][nt][0], acc[mp][nt][1]);
            *(float2*)&St[r0 + 8][c0] = make_float2(acc[mp][nt][2], acc[mp][nt][3]);
        }
    __syncthreads();
    const int tx = tid & 15, ty = tid >> 4;
    float* Sc = g_scores + (size_t)b * S * S;
    float mc[4] = {-1e38f, -1e38f, -1e38f, -1e38f};
    float ov[8][4];
#pragma unroll
    for (int r = 0; r < 8; r++) {
        const int gi = i0 + ty * 8 + r;
        const float4 v = *(const float4*)&St[ty * 8 + r][tx * 4];
        const float vv[4] = {v.x, v.y, v.z, v.w};
#pragma unroll
        for (int c = 0; c < 4; c++) {
            const int gj = j0 + tx * 4 + c;
            const float o = (gi >= gj && vv[c] > 1.0f) ? vv[c] : NEGBIG;
            ov[r][c] = o;
            mc[c] = fmaxf(mc[c], o * SCALE);
        }
    }
    float zc[4] = {0.f, 0.f, 0.f, 0.f};
#pragma unroll
    for (int r = 0; r < 8; r++) {
        const int gi = i0 + ty * 8 + r;
        *(float4*)&Sc[(size_t)gi * S + j0 + tx * 4] =
            make_float4(ov[r][0], ov[r][1], ov[r][2], ov[r][3]);
#pragma unroll
        for (int c = 0; c < 4; c++) zc[c] += __expf(ov[r][c] * SCALE - mc[c]);
    }
#pragma unroll
    for (int c = 0; c < 4; c++) {
        red_m[ty][tx * 4 + c] = mc[c];
        red_z[ty][tx * 4 + c] = zc[c];
    }
    __syncthreads();
    if (tid < 64) {
        float m = -1e38f;
#pragma unroll
        for (int t = 0; t < 16; t++) m = fmaxf(m, red_m[t][tid]);
        float z = 0.f;
#pragma unroll
        for (int t = 0; t < 16; t++) z += red_z[t][tid] * __expf(red_m[t][tid] - m);
        const size_t o = ((size_t)b * 16 + ic) * S + j0 + tid;
        g_partM[o] = m;
        g_partZ[o] = z;
    }
}

// ---- k4b: reduce 16 partials -> colC[j] = m_j + log(z_j) -------------------
__global__ __launch_bounds__(256) void k4b_reduce() {
    const int j = blockIdx.x * 256 + threadIdx.x, b = blockIdx.y;
    float pm[16], pz[16];
#pragma unroll
    for (int i = 0; i < 16; i++) {
        pm[i] = g_partM[((size_t)b * 16 + i) * S + j];
        pz[i] = g_partZ[((size_t)b * 16 + i) * S + j];
    }
    float m = -1e38f;
#pragma unroll
    for (int i = 0; i < 16; i++) m = fmaxf(m, pm[i]);
    float z = 0.f;
#pragma unroll
    for (int i = 0; i < 16; i++) z += pz[i] * __expf(pm[i] - m);
    g_colC[b * S + j] = m + logf(z);
}

// ---- k5vf: g_V fp32 -> B-frag layout (n=d, k=j), hi/lo ---------------------
__global__ __launch_bounds__(256) void k5_vfrag() {
    const int b = blockIdx.y;
    const int w = threadIdx.x >> 5, lane = threadIdx.x & 31;
    const int g = lane >> 2, q = lane & 3;
    const int nf = w, d = nf * 8 + g;
    const float* Vb = g_V + (size_t)b * S * D;
#pragma unroll
    for (int kk = 0; kk < 8; kk++) {
        const int kfj = blockIdx.x * 8 + kk;
        const int s = kfj * 16 + 2 * q;
        uint4 v;
        pack2hl(Vb[(size_t)s * D + d], Vb[(size_t)(s + 1) * D + d], v.x, v.z);
        pack2hl(Vb[(size_t)(s + 8) * D + d], Vb[(size_t)(s + 9) * D + d], v.y, v.w);
        g_fv5[((size_t)(b * 8 + nf) * 128 + kfj) * 32 + lane] = v;
    }
}

// ---- k5: HMMA out-partial = P @ V. P built in-register from scores+colC. ---
// grid (16 i-tiles, KS splits, B). 8 warps: warp = one 16-row i-frag, all d.
__global__ __launch_bounds__(256) void k5_hmma() {
    const int ic = blockIdx.x, sp = blockIdx.y, b = blockIdx.z;
    const int i0 = ic * 128;
    const int wid = threadIdx.x >> 5, lane = threadIdx.x & 31;
    const int g = lane >> 2, q = lane & 3;
    const float* Sc = g_scores + (size_t)b * S * S;
    const float* cC = g_colC + b * S;
    const int r0 = i0 + wid * 16 + g, r8 = r0 + 8;
    const float* s0p = Sc + (size_t)r0 * S;
    const float* s8p = Sc + (size_t)r8 * S;

    float acc[8][4];
#pragma unroll
    for (int nf = 0; nf < 8; nf++)
#pragma unroll
        for (int c = 0; c < 4; c++) acc[nf][c] = 0.f;

    for (int jt = sp; jt <= ic; jt += KS) {
#pragma unroll 2
        for (int kf = 0; kf < 8; kf++) {
            const int jb = jt * 128 + kf * 16;
            const float2 sa = *(const float2*)(s0p + jb + 2 * q);
            const float2 sb = *(const float2*)(s8p + jb + 2 * q);
            const float2 sc2 = *(const float2*)(s0p + jb + 8 + 2 * q);
            const float2 sd = *(const float2*)(s8p + jb + 8 + 2 * q);
            const float2 c0 = *(const float2*)(cC + jb + 2 * q);
            const float2 c1 = *(const float2*)(cC + jb + 8 + 2 * q);
            uint32_t ah[4], al[4];
            pack2hl(__expf(sa.x * SCALE - c0.x), __expf(sa.y * SCALE - c0.y), ah[0], al[0]);
            pack2hl(__expf(sb.x * SCALE - c0.x), __expf(sb.y * SCALE - c0.y), ah[1], al[1]);
            pack2hl(__expf(sc2.x * SCALE - c1.x), __expf(sc2.y * SCALE - c1.y), ah[2], al[2]);
            pack2hl(__expf(sd.x * SCALE - c1.x), __expf(sd.y * SCALE - c1.y), ah[3], al[3]);
            const uint4* vf = g_fv5 + ((size_t)(b * 8) * 128 + jt * 8 + kf) * 32 + lane;
#pragma unroll
            for (int nf = 0; nf < 8; nf++) {
                const uint4 v = vf[(size_t)nf * 128 * 32];
                hmma(acc[nf], ah, v.x, v.y);  // P_hi * V_hi
                hmma(acc[nf], ah, v.z, v.w);  // P_hi * V_lo
                hmma(acc[nf], al, v.x, v.y);  // P_lo * V_hi
            }
        }
    }
    float* P = g_part + (size_t)(sp * B + b) * S * D;
#pragma unroll
    for (int nf = 0; nf < 8; nf++) {
        const int d0 = nf * 8 + (lane & 3) * 2;
        *(float2*)(P + (size_t)r0 * D + d0) = make_float2(acc[nf][0], acc[nf][1]);
        *(float2*)(P + (size_t)r8 * D + d0) = make_float2(acc[nf][2], acc[nf][3]);
    }
}

// ---- k6: reduce KS split-K partials into d_out -----------------------------
__global__ __launch_bounds__(256) void k6_reduce(float* __restrict__ out) {
    const int idx = blockIdx.x * 256 + threadIdx.x;
    const float4* p = (const float4*)g_part;
    const size_t n4 = (size_t)B * S * D / 4;
    float4 a = p[idx];
#pragma unroll
    for (int sp = 1; sp < KS; sp++) {
        float4 q = p[sp * n4 + idx];
        a.x += q.x; a.y += q.y; a.z += q.z; a.w += q.w;
    }
    ((float4*)out)[idx] = a;
}

extern "C" void kernel_launch(void* const* d_in, const int* in_sizes, int n_in,
                              void* d_out, int out_size) {
    int xi = 0;
    for (int i = 0; i < n_in; i++)
        if (in_sizes[i] == B * S * D) { xi = i; break; }
    int o1 = -1, o2 = -1;
    for (int i = 0; i < n_in; i++)
        if (i != xi) { if (o1 < 0) o1 = i; else o2 = i; }
    const float* x = (const float*)d_in[xi];
    const float* WQ = (const float*)d_in[o1];
    const float* WV = (const float*)d_in[o2];

    k0_x<<<dim3(S / 128, B), 256>>>(x);
    k0_wv<<<S, 256>>>(WV);
    k1_suffix<<<S, 256>>>(WQ);
    k2_hmma<<<dim3(32, 8, 4), 256>>>();
    k2_reduce<<<(2 * B * S * D / 4) / 256, 256>>>();
    k3_qfrag<<<dim3(16, B), 256>>>();
    k3_hmma<<<dim3(16, 32, B), 256>>>();
    k4b_reduce<<<dim3(S / 256, B), 256>>>();
    k5_vfrag<<<dim3(16, B), 256>>>();
    k5_hmma<<<dim3(16, KS, B), 256>>>();
    k6_reduce<<<(B * S * D / 4) / 256, 256>>>((float*)d_out);
}

// round 16
// speedup vs baseline: 2.3079x; 1.0505x over previous
#include <cuda_runtime.h>
#include <cuda_bf16.h>
#include <cstdint>

namespace {
constexpr int B = 4, S = 2048, D = 64, KS = 4;
constexpr int MF = S / 16, KF = S / 16, NF = (B * D) / 8;  // 128, 128, 32
constexpr float SCALE = 0.022097086912079612f;  // 1/sqrt(2048)
constexpr float NEGBIG = -3.402823466e38f;
}

// ---- fragment-linear scratch: frag[(mf*KF+kf)*32 + lane] = uint4 ----------
__device__ uint4 g_faq_h[(size_t)MF * KF * 32];  // W_Q' hi  (a0,a1,a2,a3)
__device__ uint4 g_faq_l[(size_t)MF * KF * 32];  // W_Q' lo
__device__ uint4 g_fav_h[(size_t)MF * KF * 32];  // W_V  hi
__device__ uint4 g_fav_l[(size_t)MF * KF * 32];  // W_V  lo
__device__ uint4 g_fbx[(size_t)NF * KF * 32];    // x (k=s): (bh0,bh1,bl0,bl1)
// k3 fragments: Q as A-frags (k=d), x as B-frags (n=j, k=d)
__device__ uint4 g_fq3h[(size_t)B * 128 * 4 * 32];
__device__ uint4 g_fq3l[(size_t)B * 128 * 4 * 32];
__device__ uint4 g_fx3[(size_t)B * 256 * 4 * 32];
// k5 fragments: V as B-frags (n=d, k=j), hi/lo packed
__device__ uint4 g_fv5[(size_t)B * 8 * 128 * 32];
__device__ float g_scores[(size_t)B * S * S];
__device__ float g_partM[B * 16 * S];
__device__ float g_partZ[B * 16 * S];
__device__ float g_colC[B * S];
__device__ float g_part[(size_t)KS * B * S * D];

// ---- helpers ---------------------------------------------------------------
__device__ __forceinline__ void hmma(float* c, const uint32_t* a, uint32_t b0, uint32_t b1) {
    asm volatile(
        "mma.sync.aligned.m16n8k16.row.col.f32.bf16.bf16.f32 "
        "{%0,%1,%2,%3}, {%4,%5,%6,%7}, {%8,%9}, {%0,%1,%2,%3};"
        : "+f"(c[0]), "+f"(c[1]), "+f"(c[2]), "+f"(c[3])
        : "r"(a[0]), "r"(a[1]), "r"(a[2]), "r"(a[3]), "r"(b0), "r"(b1));
}
__device__ __forceinline__ uint32_t bpack(__nv_bfloat16 e, __nv_bfloat16 o) {
    return (uint32_t)__bfloat16_as_ushort(e) | ((uint32_t)__bfloat16_as_ushort(o) << 16);
}
__device__ __forceinline__ void bsplit(float v, __nv_bfloat16& h, __nv_bfloat16& l) {
    h = __float2bfloat16(v);
    l = __float2bfloat16(v - __bfloat162float(h));
}
__device__ __forceinline__ void pack2hl(float a, float b, uint32_t& hi, uint32_t& lo) {
    __nv_bfloat16 ha, la, hb, lb;
    bsplit(a, ha, la); bsplit(b, hb, lb);
    hi = bpack(ha, hb); lo = bpack(la, lb);
}

// writes one row's 8 consecutive-k fp32 values into A-frag layout (hi+lo)
__device__ __forceinline__ void write_a_frags(const float* wv, int row, int tid,
                                              uint32_t* outh, uint32_t* outl) {
    const int mf = row >> 4, g = row & 7;
    const int reg = (((row & 15) < 8) ? 0 : 1) + ((tid & 1) ? 2 : 0);
    const int kf = tid >> 1;
    __nv_bfloat16 h[8], l[8];
#pragma unroll
    for (int j = 0; j < 8; j++) bsplit(wv[j], h[j], l[j]);
#pragma unroll
    for (int q = 0; q < 4; q++) {
        const size_t idx = (((size_t)mf * KF + kf) * 32 + g * 4 + q) * 4 + reg;
        outh[idx] = bpack(h[2 * q], h[2 * q + 1]);
        outl[idx] = bpack(l[2 * q], l[2 * q + 1]);
    }
}

// ---- k0x: x -> k2 B-frags (k=s) AND k3 B-frags (n=j, k=d) ------------------
__global__ __launch_bounds__(256) void k0_x(const float* __restrict__ x) {
    __shared__ float t[128][65];
    const int s0 = blockIdx.x * 128, b = blockIdx.y;
    const float* xb = x + (size_t)b * S * D;
    for (int i = threadIdx.x; i < 128 * 64; i += 256)
        t[i >> 6][i & 63] = xb[(size_t)(s0 + (i >> 6)) * D + (i & 63)];
    __syncthreads();
    const int w = threadIdx.x >> 5, lane = threadIdx.x & 31;
    const int g = lane >> 2, q = lane & 3;
    {   // k2 B-frags: n = b*64+d, k = s
        const int nf = b * 8 + w, d = w * 8 + g;
#pragma unroll
        for (int kfl = 0; kfl < 8; kfl++) {
            const int sb = kfl * 16;
            uint4 v;
            pack2hl(t[sb + 2 * q][d], t[sb + 2 * q + 1][d], v.x, v.z);
            pack2hl(t[sb + 8 + 2 * q][d], t[sb + 9 + 2 * q][d], v.y, v.w);
            g_fbx[((size_t)nf * KF + (s0 >> 4) + kfl) * 32 + lane] = v;
        }
    }
    // k3 B-frags: n = j (seq), k = d. warp handles 2 nf.
#pragma unroll
    for (int r = 0; r < 2; r++) {
        const int nfl = w * 2 + r;
        const int j = nfl * 8 + g;
#pragma unroll
        for (int kf = 0; kf < 4; kf++) {
            const int d0 = kf * 16 + 2 * q;
            uint4 v;
            pack2hl(t[j][d0], t[j][d0 + 1], v.x, v.z);
            pack2hl(t[j][d0 + 8], t[j][d0 + 9], v.y, v.w);
            g_fx3[((size_t)(b * 256 + (s0 >> 3) + nfl) * 4 + kf) * 32 + lane] = v;
        }
    }
}

// ---- k0w: W_V -> A-frag layout (one block per row) -------------------------
__global__ __launch_bounds__(256) void k0_wv(const float* __restrict__ WV) {
    const int row = blockIdx.x, tid = threadIdx.x;
    const float* src = WV + (size_t)row * S + tid * 8;
    float wv[8];
#pragma unroll
    for (int j = 0; j < 8; j++) wv[j] = src[j];
    write_a_frags(wv, row, tid, (uint32_t*)g_fav_h, (uint32_t*)g_fav_l);
}

// ---- k1: W_Q'[i,u] = sum_{t>=u} W_Q[i,t]/(t+1) -> A-frag layout ------------
__global__ __launch_bounds__(256) void k1_suffix(const float* __restrict__ WQ) {
    const int row = blockIdx.x, tid = threadIdx.x, base = tid * 8;
    const float* src = WQ + (size_t)row * S;
    float v[8], local = 0.f;
#pragma unroll
    for (int k = 0; k < 8; k++) { v[k] = src[base + k] / (float)(base + k + 1); local += v[k]; }
    float pre = local;
    const int lane = tid & 31, warp = tid >> 5;
#pragma unroll
    for (int off = 1; off < 32; off <<= 1) {
        float n = __shfl_up_sync(0xffffffff, pre, off);
        if (lane >= off) pre += n;
    }
    __shared__ float wsum[8], wpre[8], stot;
    if (lane == 31) wsum[warp] = pre;
    __syncthreads();
    if (tid == 0) {
        float acc = 0.f;
#pragma unroll
        for (int w = 0; w < 8; w++) { wpre[w] = acc; acc += wsum[w]; }
        stot = acc;
    }
    __syncthreads();
    float run = wpre[warp] + (pre - local);
    float wv[8];
#pragma unroll
    for (int k = 0; k < 8; k++) { wv[k] = stot - run; run += v[k]; }
    write_a_frags(wv, row, tid, (uint32_t*)g_faq_h, (uint32_t*)g_faq_l);
}

// ---- k2: HMMA GEMM, full-K, fused fragment epilogue ------------------------
// grid (32 mt, 4 b, 2 mat). 8 warps = 4 wm x 2 wn; warp = 16 m x 32 n.
// mat=0: Q -> k3 A-frags directly (C-frag == A-frag register layout).
// mat=1: V -> k5 B-frags via smem transpose (k5_vfrag indexing, verified).
__global__ __launch_bounds__(256, 2) void k2_hmma() {
    __shared__ float Vt[64][65];
    const int mt = blockIdx.x, b = blockIdx.y, mat = blockIdx.z;
    const int wid = threadIdx.x >> 5, lane = threadIdx.x & 31;
    const int wm = wid & 3, wn = wid >> 2;
    const int mf = mt * 4 + wm;
    const int nfb = b * 8 + wn * 4;

    const uint4* Ah = (mat ? g_fav_h : g_faq_h) + (size_t)mf * KF * 32 + lane;
    const uint4* Al = (mat ? g_fav_l : g_faq_l) + (size_t)mf * KF * 32 + lane;
    const uint4* Bp[4];
#pragma unroll
    for (int nt = 0; nt < 4; nt++)
        Bp[nt] = g_fbx + (size_t)(nfb + nt) * KF * 32 + lane;

    float acc[4][4];
#pragma unroll
    for (int t = 0; t < 4; t++)
#pragma unroll
        for (int c = 0; c < 4; c++) acc[t][c] = 0.f;

#pragma unroll 4
    for (int ks = 0; ks < KF; ks++) {
        const uint4 av = Ah[ks * 32];
        const uint4 lv = Al[ks * 32];
        const uint32_t ah[4] = {av.x, av.y, av.z, av.w};
        const uint32_t al[4] = {lv.x, lv.y, lv.z, lv.w};
#pragma unroll
        for (int nt = 0; nt < 4; nt++) {
            const uint4 bb = Bp[nt][ks * 32];
            hmma(acc[nt], ah, bb.x, bb.y);  // hi*hi
            hmma(acc[nt], ah, bb.z, bb.w);  // hi*lo
            hmma(acc[nt], al, bb.x, bb.y);  // lo*hi
        }
    }
    const int g = lane >> 2, q = lane & 3;
    if (mat == 0) {
        // Q epilogue: acc (2p, 2p+1) == A-frag (a0..a3) for kf = wn*2+p
#pragma unroll
        for (int p = 0; p < 2; p++) {
            uint4 h, l;
            pack2hl(acc[2 * p][0], acc[2 * p][1], h.x, l.x);
            pack2hl(acc[2 * p][2], acc[2 * p][3], h.y, l.y);
            pack2hl(acc[2 * p + 1][0], acc[2 * p + 1][1], h.z, l.z);
            pack2hl(acc[2 * p + 1][2], acc[2 * p + 1][3], h.w, l.w);
            const size_t idx = ((size_t)(b * 128 + mf) * 4 + wn * 2 + p) * 32 + lane;
            g_fq3h[idx] = h;
            g_fq3l[idx] = l;
        }
    } else {
        // V epilogue: stage 64x64 block tile (s local = m-m0, d local = n-b*64)
#pragma unroll
        for (int nt = 0; nt < 4; nt++) {
            const int dl = wn * 32 + nt * 8 + 2 * q;
            Vt[wm * 16 + g][dl] = acc[nt][0];
            Vt[wm * 16 + g][dl + 1] = acc[nt][1];
            Vt[wm * 16 + g + 8][dl] = acc[nt][2];
            Vt[wm * 16 + g + 8][dl + 1] = acc[nt][3];
        }
        __syncthreads();
        // emit k5 B-frags: warp wid -> nf5 = wid (d = wid*8+g), kfj = mt*4+kfjl
        const int d = wid * 8 + g;
#pragma unroll
        for (int kfjl = 0; kfjl < 4; kfjl++) {
            const int sl = kfjl * 16 + 2 * q;
            uint4 v;
            pack2hl(Vt[sl][d], Vt[sl + 1][d], v.x, v.z);
            pack2hl(Vt[sl + 8][d], Vt[sl + 9][d], v.y, v.w);
            g_fv5[((size_t)(b * 8 + wid) * 128 + mt * 4 + kfjl) * 32 + lane] = v;
        }
    }
}

// ---- k3: HMMA masked scores + fused per-column (m,z) partials ---------------
__global__ __launch_bounds__(256) void k3_hmma() {
    const int ic = blockIdx.x, jc = blockIdx.y, b = blockIdx.z;
    const int i0 = ic * 128, j0 = jc * 64;
    const int tid = threadIdx.x;
    if (i0 + 127 < j0) {
        if (tid < 64) {
            const size_t o = ((size_t)b * 16 + ic) * S + j0 + tid;
            g_partM[o] = -1e38f;
            g_partZ[o] = 0.f;
        }
        return;
    }
    __shared__ float St[128][68];
    __shared__ float red_m[16][64], red_z[16][64];
    const int wid = tid >> 5, lane = tid & 31;
    const int wm = wid & 3, wn = wid >> 2;
    const int g = lane >> 2, q = lane & 3;

    float acc[2][4][4];
#pragma unroll
    for (int mp = 0; mp < 2; mp++)
#pragma unroll
        for (int nt = 0; nt < 4; nt++)
#pragma unroll
            for (int c = 0; c < 4; c++) acc[mp][nt][c] = 0.f;

    const uint4* Ah = g_fq3h + ((size_t)(b * 128 + ic * 8 + wm * 2) * 4) * 32 + lane;
    const uint4* Al = g_fq3l + ((size_t)(b * 128 + ic * 8 + wm * 2) * 4) * 32 + lane;
    const uint4* Bf = g_fx3 + ((size_t)(b * 256 + jc * 8 + wn * 4) * 4) * 32 + lane;

#pragma unroll
    for (int kf = 0; kf < 4; kf++) {
        const uint4 a0 = Ah[kf * 32], a1 = Ah[(4 + kf) * 32];
        const uint4 l0 = Al[kf * 32], l1 = Al[(4 + kf) * 32];
        const uint32_t ah0[4] = {a0.x, a0.y, a0.z, a0.w};
        const uint32_t ah1[4] = {a1.x, a1.y, a1.z, a1.w};
        const uint32_t al0[4] = {l0.x, l0.y, l0.z, l0.w};
        const uint32_t al1[4] = {l1.x, l1.y, l1.z, l1.w};
#pragma unroll
        for (int nt = 0; nt < 4; nt++) {
            const uint4 bb = Bf[(nt * 4 + kf) * 32];
            hmma(acc[0][nt], ah0, bb.x, bb.y);
            hmma(acc[0][nt], ah0, bb.z, bb.w);
            hmma(acc[0][nt], al0, bb.x, bb.y);
            hmma(acc[1][nt], ah1, bb.x, bb.y);
            hmma(acc[1][nt], ah1, bb.z, bb.w);
            hmma(acc[1][nt], al1, bb.x, bb.y);
        }
    }
#pragma unroll
    for (int mp = 0; mp < 2; mp++)
#pragma unroll
        for (int nt = 0; nt < 4; nt++) {
            const int r0 = wm * 32 + mp * 16 + g, c0 = wn * 32 + nt * 8 + 2 * q;
            *(float2*)&St[r0][c0] = make_float2(acc[mp][nt][0], acc[mp][nt][1]);
            *(float2*)&St[r0 + 8][c0] = make_float2(acc[mp][nt][2], acc[mp][nt][3]);
        }
    __syncthreads();
    const int tx = tid & 15, ty = tid >> 4;
    float* Sc = g_scores + (size_t)b * S * S;
    float mc[4] = {-1e38f, -1e38f, -1e38f, -1e38f};
    float ov[8][4];
#pragma unroll
    for (int r = 0; r < 8; r++) {
        const int gi = i0 + ty * 8 + r;
        const float4 v = *(const float4*)&St[ty * 8 + r][tx * 4];
        const float vv[4] = {v.x, v.y, v.z, v.w};
#pragma unroll
        for (int c = 0; c < 4; c++) {
            const int gj = j0 + tx * 4 + c;
            const float o = (gi >= gj && vv[c] > 1.0f) ? vv[c] : NEGBIG;
            ov[r][c] = o;
            mc[c] = fmaxf(mc[c], o * SCALE);
        }
    }
    float zc[4] = {0.f, 0.f, 0.f, 0.f};
#pragma unroll
    for (int r = 0; r < 8; r++) {
        const int gi = i0 + ty * 8 + r;
        *(float4*)&Sc[(size_t)gi * S + j0 + tx * 4] =
            make_float4(ov[r][0], ov[r][1], ov[r][2], ov[r][3]);
#pragma unroll
        for (int c = 0; c < 4; c++) zc[c] += __expf(ov[r][c] * SCALE - mc[c]);
    }
#pragma unroll
    for (int c = 0; c < 4; c++) {
        red_m[ty][tx * 4 + c] = mc[c];
        red_z[ty][tx * 4 + c] = zc[c];
    }
    __syncthreads();
    if (tid < 64) {
        float m = -1e38f;
#pragma unroll
        for (int t = 0; t < 16; t++) m = fmaxf(m, red_m[t][tid]);
        float z = 0.f;
#pragma unroll
        for (int t = 0; t < 16; t++) z += red_z[t][tid] * __expf(red_m[t][tid] - m);
        const size_t o = ((size_t)b * 16 + ic) * S + j0 + tid;
        g_partM[o] = m;
        g_partZ[o] = z;
    }
}

// ---- k4b: reduce 16 partials -> colC[j] = m_j + log(z_j) -------------------
__global__ __launch_bounds__(256) void k4b_reduce() {
    const int j = blockIdx.x * 256 + threadIdx.x, b = blockIdx.y;
    float pm[16], pz[16];
#pragma unroll
    for (int i = 0; i < 16; i++) {
        pm[i] = g_partM[((size_t)b * 16 + i) * S + j];
        pz[i] = g_partZ[((size_t)b * 16 + i) * S + j];
    }
    float m = -1e38f;
#pragma unroll
    for (int i = 0; i < 16; i++) m = fmaxf(m, pm[i]);
    float z = 0.f;
#pragma unroll
    for (int i = 0; i < 16; i++) z += pz[i] * __expf(pm[i] - m);
    g_colC[b * S + j] = m + logf(z);
}

// ---- k5: HMMA out-partial = P @ V. P built in-register from scores+colC. ---
__global__ __launch_bounds__(256) void k5_hmma() {
    const int ic = blockIdx.x, sp = blockIdx.y, b = blockIdx.z;
    const int i0 = ic * 128;
    const int wid = threadIdx.x >> 5, lane = threadIdx.x & 31;
    const int g = lane >> 2, q = lane & 3;
    const float* Sc = g_scores + (size_t)b * S * S;
    const float* cC = g_colC + b * S;
    const int r0 = i0 + wid * 16 + g, r8 = r0 + 8;
    const float* s0p = Sc + (size_t)r0 * S;
    const float* s8p = Sc + (size_t)r8 * S;

    float acc[8][4];
#pragma unroll
    for (int nf = 0; nf < 8; nf++)
#pragma unroll
        for (int c = 0; c < 4; c++) acc[nf][c] = 0.f;

    for (int jt = sp; jt <= ic; jt += KS) {
#pragma unroll 2
        for (int kf = 0; kf < 8; kf++) {
            const int jb = jt * 128 + kf * 16;
            const float2 sa = *(const float2*)(s0p + jb + 2 * q);
            const float2 sb = *(const float2*)(s8p + jb + 2 * q);
            const float2 sc2 = *(const float2*)(s0p + jb + 8 + 2 * q);
            const float2 sd = *(const float2*)(s8p + jb + 8 + 2 * q);
            const float2 c0 = *(const float2*)(cC + jb + 2 * q);
            const float2 c1 = *(const float2*)(cC + jb + 8 + 2 * q);
            uint32_t ah[4], al[4];
            pack2hl(__expf(sa.x * SCALE - c0.x), __expf(sa.y * SCALE - c0.y), ah[0], al[0]);
            pack2hl(__expf(sb.x * SCALE - c0.x), __expf(sb.y * SCALE - c0.y), ah[1], al[1]);
            pack2hl(__expf(sc2.x * SCALE - c1.x), __expf(sc2.y * SCALE - c1.y), ah[2], al[2]);
            pack2hl(__expf(sd.x * SCALE - c1.x), __expf(sd.y * SCALE - c1.y), ah[3], al[3]);
            const uint4* vf = g_fv5 + ((size_t)(b * 8) * 128 + jt * 8 + kf) * 32 + lane;
#pragma unroll
            for (int nf = 0; nf < 8; nf++) {
                const uint4 v = vf[(size_t)nf * 128 * 32];
                hmma(acc[nf], ah, v.x, v.y);  // P_hi * V_hi
                hmma(acc[nf], ah, v.z, v.w);  // P_hi * V_lo
                hmma(acc[nf], al, v.x, v.y);  // P_lo * V_hi
            }
        }
    }
    float* P = g_part + (size_t)(sp * B + b) * S * D;
#pragma unroll
    for (int nf = 0; nf < 8; nf++) {
        const int d0 = nf * 8 + (lane & 3) * 2;
        *(float2*)(P + (size_t)r0 * D + d0) = make_float2(acc[nf][0], acc[nf][1]);
        *(float2*)(P + (size_t)r8 * D + d0) = make_float2(acc[nf][2], acc[nf][3]);
    }
}

// ---- k6: reduce KS split-K partials into d_out -----------------------------
__global__ __launch_bounds__(256) void k6_reduce(float* __restrict__ out) {
    const int idx = blockIdx.x * 256 + threadIdx.x;
    const float4* p = (const float4*)g_part;
    const size_t n4 = (size_t)B * S * D / 4;
    float4 a = p[idx];
#pragma unroll
    for (int sp = 1; sp < KS; sp++) {
        float4 q = p[sp * n4 + idx];
        a.x += q.x; a.y += q.y; a.z += q.z; a.w += q.w;
    }
    ((float4*)out)[idx] = a;
}

extern "C" void kernel_launch(void* const* d_in, const int* in_sizes, int n_in,
                              void* d_out, int out_size) {
    int xi = 0;
    for (int i = 0; i < n_in; i++)
        if (in_sizes[i] == B * S * D) { xi = i; break; }
    int o1 = -1, o2 = -1;
    for (int i = 0; i < n_in; i++)
        if (i != xi) { if (o1 < 0) o1 = i; else o2 = i; }
    const float* x = (const float*)d_in[xi];
    const float* WQ = (const float*)d_in[o1];
    const float* WV = (const float*)d_in[o2];

    k0_x<<<dim3(S / 128, B), 256>>>(x);
    k0_wv<<<S, 256>>>(WV);
    k1_suffix<<<S, 256>>>(WQ);
    k2_hmma<<<dim3(32, B, 2), 256>>>();
    k3_hmma<<<dim3(16, 32, B), 256>>>();
    k4b_reduce<<<dim3(S / 256, B), 256>>>();
    k5_hmma<<<dim3(16, KS, B), 256>>>();
    k6_reduce<<<(B * S * D / 4) / 256, 256>>>((float*)d_out);
}